// round 2
// baseline (speedup 1.0000x reference)
#include <cuda_runtime.h>
#include <math.h>

#define BATCH 16
#define CCH   128
#define NDIM  2000
#define SST   8
#define DCONVK 4
#define DIX   4000
#define DTR   125
#define XCOLS 141     // DTR + 2*SST
#define LSEQ  128     // sequence length for mamba = CCH
#define ROWS  2048    // BATCH*CCH = BATCH*LSEQ
#define DIN2  8000    // 2*DIX

// ---------------- scratch (static device memory; no allocations) -------------
__device__ float g_m1[ROWS], g_r1[ROWS];
__device__ float g_cm1[CCH], g_cr1[CCH];
__device__ float g_mL[ROWS], g_rL[ROWS];
__device__ float g_m3[ROWS], g_r3[ROWS];
__device__ float g_cm3[CCH], g_cr3[CCH];
__device__ float g_h   [(size_t)ROWS*NDIM];
__device__ float g_h1  [(size_t)ROWS*NDIM];
__device__ float g_outn[(size_t)ROWS*NDIM];
__device__ float g_xz  [(size_t)ROWS*DIN2];
__device__ float g_xc  [(size_t)ROWS*DIX];
__device__ float g_xdbl[(size_t)ROWS*XCOLS];
__device__ float g_dt  [(size_t)ROWS*DIX];
__device__ float g_y   [(size_t)ROWS*DIX];
__device__ float g_res [(size_t)ROWS*NDIM];

// ---------------- reductions -------------------------------------------------
__device__ __forceinline__ void block_reduce2(float& s, float& s2) {
    __shared__ float sh[16];
    #pragma unroll
    for (int o = 16; o; o >>= 1) {
        s  += __shfl_down_sync(0xffffffffu, s,  o);
        s2 += __shfl_down_sync(0xffffffffu, s2, o);
    }
    int w = threadIdx.x >> 5, lane = threadIdx.x & 31;
    if (lane == 0) { sh[w] = s; sh[8 + w] = s2; }
    __syncthreads();
    if (threadIdx.x == 0) {
        float S = 0.f, S2 = 0.f;
        int nw = blockDim.x >> 5;
        for (int i = 0; i < nw; i++) { S += sh[i]; S2 += sh[8 + i]; }
        sh[0] = S; sh[8] = S2;
    }
    __syncthreads();
    s = sh[0]; s2 = sh[8];
}

// per-row mean/rstd over last dim L
__global__ void rowstat_kernel(const float* __restrict__ x, float* __restrict__ mean,
                               float* __restrict__ rstd, int L, float eps) {
    int row = blockIdx.x;
    const float* p = x + (size_t)row * L;
    float s = 0.f, s2 = 0.f;
    for (int i = threadIdx.x; i < L; i += blockDim.x) {
        float v = p[i]; s += v; s2 += v * v;
    }
    block_reduce2(s, s2);
    if (threadIdx.x == 0) {
        float m = s / L;
        float var = s2 / L - m * m;
        mean[row] = m;
        rstd[row] = rsqrtf(var + eps);
    }
}

// per-channel stats of instance-normalized x over (b, n)
__global__ void chanstat_kernel(const float* __restrict__ x, const float* __restrict__ m,
                                const float* __restrict__ r, float* __restrict__ cmean,
                                float* __restrict__ crstd, float eps) {
    int c = blockIdx.x;
    float s = 0.f, s2 = 0.f;
    for (int idx = threadIdx.x; idx < BATCH * NDIM; idx += blockDim.x) {
        int b = idx / NDIM, n = idx - b * NDIM;
        int row = b * CCH + c;
        float v = (x[(size_t)row * NDIM + n] - m[row]) * r[row];
        s += v; s2 += v * v;
    }
    block_reduce2(s, s2);
    if (threadIdx.x == 0) {
        float mm = s / (BATCH * NDIM);
        float var = s2 / (BATCH * NDIM) - mm * mm;
        cmean[c] = mm;
        crstd[c] = rsqrtf(var + eps);
    }
}

// h = relu( ((x - m)*r - cm[c]) * cr[c] * g[c] + b[c] )
__global__ void normrelu_kernel(const float* __restrict__ x, const float* __restrict__ m,
                                const float* __restrict__ r, const float* __restrict__ cm,
                                const float* __restrict__ cr, const float* __restrict__ g,
                                const float* __restrict__ bb, float* __restrict__ out) {
    size_t i = (size_t)blockIdx.x * blockDim.x + threadIdx.x;
    if (i >= (size_t)ROWS * NDIM) return;
    int row = (int)(i / NDIM);
    int c = row & (CCH - 1);
    float v = (x[i] - m[row]) * r[row];
    v = (v - cm[c]) * cr[c] * g[c] + bb[c];
    out[i] = fmaxf(v, 0.f);
}

// layernorm apply: out = (x - m)*r * w[n] + b[n]
__global__ void lnapply_kernel(const float* __restrict__ x, const float* __restrict__ m,
                               const float* __restrict__ r, const float* __restrict__ w,
                               const float* __restrict__ bb, float* __restrict__ out) {
    size_t i = (size_t)blockIdx.x * blockDim.x + threadIdx.x;
    if (i >= (size_t)ROWS * NDIM) return;
    int row = (int)(i / NDIM);
    int n = (int)(i - (size_t)row * NDIM);
    out[i] = (x[i] - m[row]) * r[row] * w[n] + bb[n];
}

// depthwise causal conv over L + silu;  xi = first half of xz rows
__global__ void convm_silu_kernel(const float* __restrict__ xz, const float* __restrict__ cw,
                                  const float* __restrict__ cb, float* __restrict__ xc) {
    size_t i = (size_t)blockIdx.x * blockDim.x + threadIdx.x;
    if (i >= (size_t)ROWS * DIX) return;
    int d = (int)(i % DIX);
    size_t mrow = i / DIX;            // b*LSEQ + l
    int l = (int)(mrow & (LSEQ - 1));
    size_t b = mrow >> 7;             // LSEQ = 128
    float acc = cb[d];
    #pragma unroll
    for (int k = 0; k < DCONVK; k++) {
        int ls = l + k - (DCONVK - 1);
        if (ls >= 0)
            acc += xz[(b * LSEQ + ls) * (size_t)DIN2 + d] * cw[d * DCONVK + k];
    }
    xc[i] = acc * (1.f / (1.f + expf(-acc)));
}

// selective scan; fuses  y = (scan + xc*D) * silu(z)
__global__ void scan_kernel(const float* __restrict__ dt, const float* __restrict__ xc,
                            const float* __restrict__ xdbl, const float* __restrict__ xz,
                            const float* __restrict__ A_log, const float* __restrict__ D_p,
                            float* __restrict__ y) {
    int gidx = blockIdx.x * blockDim.x + threadIdx.x;
    if (gidx >= BATCH * DIX) return;
    int b = gidx / DIX, d = gidx - b * DIX;
    float A[SST], h[SST];
    #pragma unroll
    for (int s = 0; s < SST; s++) {
        A[s] = -expf(A_log[d * SST + s]);
        h[s] = 0.f;
    }
    float Dp = D_p[d];
    for (int l = 0; l < LSEQ; l++) {
        size_t m = (size_t)b * LSEQ + l;
        float dtv = dt[m * DIX + d];
        float u = xc[m * DIX + d];
        float du = dtv * u;
        const float* xr = xdbl + m * XCOLS;
        float yv = 0.f;
        #pragma unroll
        for (int s = 0; s < SST; s++) {
            h[s] = __expf(dtv * A[s]) * h[s] + du * xr[DTR + s];
            yv += h[s] * xr[DTR + SST + s];
        }
        float zv = xz[m * DIN2 + DIX + d];
        y[m * DIX + d] = (yv + u * Dp) * (zv / (1.f + __expf(-zv)));
    }
}

// ---------------- generic tiled SGEMM ---------------------------------------
// C[m,n] = sum_k A[m,k] * (transB ? B[n,k] : B[k,n])  (+biasM/+biasN/+resid, act)
__global__ void __launch_bounds__(256) gemm_kernel(
    const float* __restrict__ A, const float* __restrict__ Bp, float* __restrict__ C,
    int M, int N, int K, int lda, int ldb, int ldc,
    long sA, long sB, long sC, int transB,
    const float* __restrict__ biasM, const float* __restrict__ biasN,
    const float* __restrict__ resid, long sR, int act) {
    __shared__ float As[16][132];
    __shared__ float Bs[16][132];
    int z = blockIdx.z;
    A  += (long)z * sA;
    Bp += (long)z * sB;
    C  += (long)z * sC;
    int m0 = blockIdx.y * 128, n0 = blockIdx.x * 128;
    int tid = threadIdx.x;
    int tx = tid & 15, ty = tid >> 4;

    float acc[8][8];
    #pragma unroll
    for (int i = 0; i < 8; i++)
        #pragma unroll
        for (int j = 0; j < 8; j++) acc[i][j] = 0.f;

    int mrow[8], ncol[8];
    #pragma unroll
    for (int i = 0; i < 8; i++) {
        mrow[i] = (i < 4) ? ty * 4 + i : 64 + ty * 4 + (i - 4);
        ncol[i] = (i < 4) ? tx * 4 + i : 64 + tx * 4 + (i - 4);
    }

    for (int k0 = 0; k0 < K; k0 += 16) {
        #pragma unroll
        for (int j = 0; j < 8; j++) {
            int i = tid * 8 + j;
            int mm = i >> 4, kk = i & 15;
            int gm = m0 + mm, gk = k0 + kk;
            As[kk][mm] = (gm < M && gk < K) ? A[(long)gm * lda + gk] : 0.f;
        }
        if (transB) {
            #pragma unroll
            for (int j = 0; j < 8; j++) {
                int i = tid * 8 + j;
                int nn = i >> 4, kk = i & 15;
                int gn = n0 + nn, gk = k0 + kk;
                Bs[kk][nn] = (gn < N && gk < K) ? Bp[(long)gn * ldb + gk] : 0.f;
            }
        } else {
            #pragma unroll
            for (int j = 0; j < 8; j++) {
                int i = tid * 8 + j;
                int kk = i >> 7, nn = i & 127;
                int gk = k0 + kk, gn = n0 + nn;
                Bs[kk][nn] = (gk < K && gn < N) ? Bp[(long)gk * ldb + gn] : 0.f;
            }
        }
        __syncthreads();
        #pragma unroll
        for (int k = 0; k < 16; k++) {
            float ra[8], rb[8];
            #pragma unroll
            for (int i = 0; i < 8; i++) ra[i] = As[k][mrow[i]];
            #pragma unroll
            for (int j = 0; j < 8; j++) rb[j] = Bs[k][ncol[j]];
            #pragma unroll
            for (int i = 0; i < 8; i++)
                #pragma unroll
                for (int j = 0; j < 8; j++)
                    acc[i][j] = fmaf(ra[i], rb[j], acc[i][j]);
        }
        __syncthreads();
    }

    if (resid) resid += (long)z * sR;
    #pragma unroll
    for (int i = 0; i < 8; i++) {
        int gm = m0 + mrow[i];
        if (gm >= M) continue;
        float bm = biasM ? biasM[gm] : 0.f;
        #pragma unroll
        for (int j = 0; j < 8; j++) {
            int gn = n0 + ncol[j];
            if (gn >= N) continue;
            float v = acc[i][j] + bm;
            if (biasN) v += biasN[gn];
            if (resid) v += resid[(long)gm * ldc + gn];
            if (act == 2) v = (v > 20.f) ? v : log1pf(expf(v));
            C[(long)gm * ldc + gn] = v;
        }
    }
}

// ---------------- host side --------------------------------------------------
static void launch_gemm(const float* A, const float* B, float* C,
                        int M, int N, int K, int lda, int ldb, int ldc,
                        long sA, long sB, long sC, int batch, int transB,
                        const float* biasM, const float* biasN,
                        const float* resid, long sR, int act) {
    dim3 grid((N + 127) / 128, (M + 127) / 128, batch);
    gemm_kernel<<<grid, 256>>>(A, B, C, M, N, K, lda, ldb, ldc,
                               sA, sB, sC, transB, biasM, biasN, resid, sR, act);
}

extern "C" void kernel_launch(void* const* d_in, const int* in_sizes, int n_in,
                              void* d_out, int out_size) {
    const float* x       = (const float*)d_in[0];
    const float* bn1_g   = (const float*)d_in[1];
    const float* bn1_b   = (const float*)d_in[2];
    const float* conv1_w = (const float*)d_in[3];
    const float* conv1_b = (const float*)d_in[4];
    const float* ln_w    = (const float*)d_in[5];
    const float* ln_b    = (const float*)d_in[6];
    const float* W_in    = (const float*)d_in[7];
    const float* convm_w = (const float*)d_in[8];
    const float* convm_b = (const float*)d_in[9];
    const float* W_x     = (const float*)d_in[10];
    const float* W_dt    = (const float*)d_in[11];
    const float* b_dt    = (const float*)d_in[12];
    const float* A_log   = (const float*)d_in[13];
    const float* D_p     = (const float*)d_in[14];
    const float* W_out   = (const float*)d_in[15];
    const float* bn3_g   = (const float*)d_in[16];
    const float* bn3_b   = (const float*)d_in[17];
    const float* conv3_w = (const float*)d_in[18];
    const float* conv3_b = (const float*)d_in[19];
    float* out = (float*)d_out;

    float *pm1, *pr1, *pcm1, *pcr1, *pmL, *prL, *pm3, *pr3, *pcm3, *pcr3;
    float *ph, *ph1, *poutn, *pxz, *pxc, *pxdbl, *pdt, *py, *pres;
    cudaGetSymbolAddress((void**)&pm1,  g_m1);
    cudaGetSymbolAddress((void**)&pr1,  g_r1);
    cudaGetSymbolAddress((void**)&pcm1, g_cm1);
    cudaGetSymbolAddress((void**)&pcr1, g_cr1);
    cudaGetSymbolAddress((void**)&pmL,  g_mL);
    cudaGetSymbolAddress((void**)&prL,  g_rL);
    cudaGetSymbolAddress((void**)&pm3,  g_m3);
    cudaGetSymbolAddress((void**)&pr3,  g_r3);
    cudaGetSymbolAddress((void**)&pcm3, g_cm3);
    cudaGetSymbolAddress((void**)&pcr3, g_cr3);
    cudaGetSymbolAddress((void**)&ph,    g_h);
    cudaGetSymbolAddress((void**)&ph1,   g_h1);
    cudaGetSymbolAddress((void**)&poutn, g_outn);
    cudaGetSymbolAddress((void**)&pxz,   g_xz);
    cudaGetSymbolAddress((void**)&pxc,   g_xc);
    cudaGetSymbolAddress((void**)&pxdbl, g_xdbl);
    cudaGetSymbolAddress((void**)&pdt,   g_dt);
    cudaGetSymbolAddress((void**)&py,    g_y);
    cudaGetSymbolAddress((void**)&pres,  g_res);

    const int EW_BLK = 256;
    const size_t nBCN = (size_t)ROWS * NDIM;       // 4,096,000
    const size_t nBLD = (size_t)ROWS * DIX;        // 8,192,000
    int gBCN = (int)((nBCN + EW_BLK - 1) / EW_BLK);
    int gBLD = (int)((nBLD + EW_BLK - 1) / EW_BLK);

    // ---- Block 1: inorm -> bnorm -> relu -> 1x1 conv ----
    rowstat_kernel<<<ROWS, 256>>>(x, pm1, pr1, NDIM, 1e-3f);
    chanstat_kernel<<<CCH, 256>>>(x, pm1, pr1, pcm1, pcr1, 1e-5f);
    normrelu_kernel<<<gBCN, EW_BLK>>>(x, pm1, pr1, pcm1, pcr1, bn1_g, bn1_b, ph);
    launch_gemm(conv1_w, ph, ph1, CCH, NDIM, CCH, CCH, NDIM, NDIM,
                0, (long)CCH * NDIM, (long)CCH * NDIM, BATCH, 0,
                conv1_b, nullptr, nullptr, 0, 0);

    // ---- LayerNorm over N ----
    rowstat_kernel<<<ROWS, 256>>>(ph1, pmL, prL, NDIM, 1e-5f);
    lnapply_kernel<<<gBCN, EW_BLK>>>(ph1, pmL, prL, ln_w, ln_b, poutn);

    // ---- Mamba ----
    // xz = out_n @ W_in^T   [2048 x 8000]
    launch_gemm(poutn, W_in, pxz, ROWS, DIN2, NDIM, NDIM, NDIM, DIN2,
                0, 0, 0, 1, 1, nullptr, nullptr, nullptr, 0, 0);
    // depthwise conv + silu -> xc [2048 x 4000]
    convm_silu_kernel<<<gBLD, EW_BLK>>>(pxz, convm_w, convm_b, pxc);
    // xdbl = xc @ W_x^T   [2048 x 141]
    launch_gemm(pxc, W_x, pxdbl, ROWS, XCOLS, DIX, DIX, DIX, XCOLS,
                0, 0, 0, 1, 1, nullptr, nullptr, nullptr, 0, 0);
    // dt = softplus(xdbl[:, :125] @ W_dt^T + b_dt)  [2048 x 4000]
    launch_gemm(pxdbl, W_dt, pdt, ROWS, DIX, DTR, XCOLS, DTR, DIX,
                0, 0, 0, 1, 1, nullptr, b_dt, nullptr, 0, 2);
    // scan + gating
    scan_kernel<<<(BATCH * DIX + 255) / 256, 256>>>(pdt, pxc, pxdbl, pxz,
                                                    A_log, D_p, py);
    // res = h1 + y @ W_out^T   [2048 x 2000]
    launch_gemm(py, W_out, pres, ROWS, NDIM, DIX, DIX, DIX, NDIM,
                0, 0, 0, 1, 1, nullptr, nullptr, ph1, 0, 0);

    // ---- Block 3: inorm -> bnorm -> relu -> 1x1 conv, + input residual ----
    rowstat_kernel<<<ROWS, 256>>>(pres, pm3, pr3, NDIM, 1e-3f);
    chanstat_kernel<<<CCH, 256>>>(pres, pm3, pr3, pcm3, pcr3, 1e-5f);
    normrelu_kernel<<<gBCN, EW_BLK>>>(pres, pm3, pr3, pcm3, pcr3, bn3_g, bn3_b, ph);
    launch_gemm(conv3_w, ph, out, CCH, NDIM, CCH, CCH, NDIM, NDIM,
                0, (long)CCH * NDIM, (long)CCH * NDIM, BATCH, 0,
                conv3_b, nullptr, x, (long)CCH * NDIM, 0);
}

// round 5
// speedup vs baseline: 1.7967x; 1.7967x over previous
#include <cuda_runtime.h>
#include <math.h>
#include <stdint.h>

#define BATCH 16
#define CCH   128
#define NDIM  2000
#define SST   8
#define DCONVK 4
#define DIX   4000
#define DTR   125
#define XCOLS 141     // DTR + 2*SST
#define LSEQ  128     // sequence length for mamba = CCH
#define ROWS  2048    // BATCH*CCH = BATCH*LSEQ
#define DIN2  8000    // 2*DIX

// ---------------- scratch (static device memory; no allocations) -------------
__device__ float g_m1[ROWS], g_r1[ROWS];
__device__ float g_cm1[CCH], g_cr1[CCH];
__device__ float g_mL[ROWS], g_rL[ROWS];
__device__ float g_m3[ROWS], g_r3[ROWS];
__device__ float g_cm3[CCH], g_cr3[CCH];
__device__ float g_h   [(size_t)ROWS*NDIM];
__device__ float g_h1  [(size_t)ROWS*NDIM];
__device__ float g_outn[(size_t)ROWS*NDIM];
__device__ float g_xz  [(size_t)ROWS*DIN2];
__device__ float g_xc  [(size_t)ROWS*DIX];
__device__ float g_xdbl[(size_t)ROWS*XCOLS];
__device__ float g_dt  [(size_t)ROWS*DIX];
__device__ float g_y   [(size_t)ROWS*DIX];
__device__ float g_res [(size_t)ROWS*NDIM];

// ---------------- reductions -------------------------------------------------
__device__ __forceinline__ void block_reduce2(float& s, float& s2) {
    __shared__ float sh[16];
    #pragma unroll
    for (int o = 16; o; o >>= 1) {
        s  += __shfl_down_sync(0xffffffffu, s,  o);
        s2 += __shfl_down_sync(0xffffffffu, s2, o);
    }
    int w = threadIdx.x >> 5, lane = threadIdx.x & 31;
    if (lane == 0) { sh[w] = s; sh[8 + w] = s2; }
    __syncthreads();
    if (threadIdx.x == 0) {
        float S = 0.f, S2 = 0.f;
        int nw = blockDim.x >> 5;
        for (int i = 0; i < nw; i++) { S += sh[i]; S2 += sh[8 + i]; }
        sh[0] = S; sh[8] = S2;
    }
    __syncthreads();
    s = sh[0]; s2 = sh[8];
}

__global__ void rowstat_kernel(const float* __restrict__ x, float* __restrict__ mean,
                               float* __restrict__ rstd, int L, float eps) {
    int row = blockIdx.x;
    const float* p = x + (size_t)row * L;
    float s = 0.f, s2 = 0.f;
    for (int i = threadIdx.x; i < L; i += blockDim.x) {
        float v = p[i]; s += v; s2 += v * v;
    }
    block_reduce2(s, s2);
    if (threadIdx.x == 0) {
        float m = s / L;
        float var = s2 / L - m * m;
        mean[row] = m;
        rstd[row] = rsqrtf(var + eps);
    }
}

__global__ void chanstat_kernel(const float* __restrict__ x, const float* __restrict__ m,
                                const float* __restrict__ r, float* __restrict__ cmean,
                                float* __restrict__ crstd, float eps) {
    int c = blockIdx.x;
    float s = 0.f, s2 = 0.f;
    for (int idx = threadIdx.x; idx < BATCH * NDIM; idx += blockDim.x) {
        int b = idx / NDIM, n = idx - b * NDIM;
        int row = b * CCH + c;
        float v = (x[(size_t)row * NDIM + n] - m[row]) * r[row];
        s += v; s2 += v * v;
    }
    block_reduce2(s, s2);
    if (threadIdx.x == 0) {
        float mm = s / (BATCH * NDIM);
        float var = s2 / (BATCH * NDIM) - mm * mm;
        cmean[c] = mm;
        crstd[c] = rsqrtf(var + eps);
    }
}

__global__ void normrelu_kernel(const float* __restrict__ x, const float* __restrict__ m,
                                const float* __restrict__ r, const float* __restrict__ cm,
                                const float* __restrict__ cr, const float* __restrict__ g,
                                const float* __restrict__ bb, float* __restrict__ out) {
    size_t i = (size_t)blockIdx.x * blockDim.x + threadIdx.x;
    if (i >= (size_t)ROWS * NDIM) return;
    int row = (int)(i / NDIM);
    int c = row & (CCH - 1);
    float v = (x[i] - m[row]) * r[row];
    v = (v - cm[c]) * cr[c] * g[c] + bb[c];
    out[i] = fmaxf(v, 0.f);
}

__global__ void lnapply_kernel(const float* __restrict__ x, const float* __restrict__ m,
                               const float* __restrict__ r, const float* __restrict__ w,
                               const float* __restrict__ bb, float* __restrict__ out) {
    size_t i = (size_t)blockIdx.x * blockDim.x + threadIdx.x;
    if (i >= (size_t)ROWS * NDIM) return;
    int row = (int)(i / NDIM);
    int n = (int)(i - (size_t)row * NDIM);
    out[i] = (x[i] - m[row]) * r[row] * w[n] + bb[n];
}

__global__ void convm_silu_kernel(const float* __restrict__ xz, const float* __restrict__ cw,
                                  const float* __restrict__ cb, float* __restrict__ xc) {
    size_t i = (size_t)blockIdx.x * blockDim.x + threadIdx.x;
    if (i >= (size_t)ROWS * DIX) return;
    int d = (int)(i % DIX);
    size_t mrow = i / DIX;
    int l = (int)(mrow & (LSEQ - 1));
    size_t b = mrow >> 7;
    float acc = cb[d];
    #pragma unroll
    for (int k = 0; k < DCONVK; k++) {
        int ls = l + k - (DCONVK - 1);
        if (ls >= 0)
            acc += xz[(b * LSEQ + ls) * (size_t)DIN2 + d] * cw[d * DCONVK + k];
    }
    xc[i] = acc * (1.f / (1.f + __expf(-acc)));
}

__global__ void scan_kernel(const float* __restrict__ dt, const float* __restrict__ xc,
                            const float* __restrict__ xdbl, const float* __restrict__ xz,
                            const float* __restrict__ A_log, const float* __restrict__ D_p,
                            float* __restrict__ y) {
    int gidx = blockIdx.x * blockDim.x + threadIdx.x;
    if (gidx >= BATCH * DIX) return;
    int b = gidx / DIX, d = gidx - b * DIX;
    float A[SST], h[SST];
    #pragma unroll
    for (int s = 0; s < SST; s++) {
        A[s] = -expf(A_log[d * SST + s]);
        h[s] = 0.f;
    }
    float Dp = D_p[d];
    for (int l = 0; l < LSEQ; l++) {
        size_t m = (size_t)b * LSEQ + l;
        float dtv = dt[m * DIX + d];
        float u = xc[m * DIX + d];
        float du = dtv * u;
        const float* xr = xdbl + m * XCOLS;
        float yv = 0.f;
        #pragma unroll
        for (int s = 0; s < SST; s++) {
            h[s] = __expf(dtv * A[s]) * h[s] + du * xr[DTR + s];
            yv += h[s] * xr[DTR + SST + s];
        }
        float zv = xz[m * DIN2 + DIX + d];
        y[m * DIX + d] = (yv + u * Dp) * (zv / (1.f + __expf(-zv)));
    }
}

// ---------------- TF32 tensor-core GEMM --------------------------------------
// C[m,n] = sum_k A[m,k] * (transB ? B[n,k] : B[k,n])  (+biasM/+biasN/+resid, act)
// 128x128 tile, BK=16, 8 warps (4m x 2n), each warp 32x64 via m16n8k8 tf32 mma.

#define ASTR 20    // As row stride (floats), 128 rows
#define BSTR 136   // Bs row stride (floats), 16 rows

__device__ __forceinline__ uint32_t f2tf(float x) {
    uint32_t r;
    asm("cvt.rna.tf32.f32 %0, %1;" : "=r"(r) : "f"(x));
    return r;
}

__device__ __forceinline__ void mma_tf32(float* c, const uint32_t* a, const uint32_t* b) {
    asm volatile(
        "mma.sync.aligned.m16n8k8.row.col.f32.tf32.tf32.f32 "
        "{%0,%1,%2,%3}, {%4,%5,%6,%7}, {%8,%9}, {%0,%1,%2,%3};\n"
        : "+f"(c[0]), "+f"(c[1]), "+f"(c[2]), "+f"(c[3])
        : "r"(a[0]), "r"(a[1]), "r"(a[2]), "r"(a[3]), "r"(b[0]), "r"(b[1]));
}

__global__ void __launch_bounds__(256, 2) gemm_tf32_kernel(
    const float* __restrict__ A, const float* __restrict__ Bp, float* __restrict__ C,
    int M, int N, int K, int lda, int ldb, int ldc,
    long sA, long sB, long sC, int transB,
    const float* __restrict__ biasM, const float* __restrict__ biasN,
    const float* __restrict__ resid, long sR, int act) {
    __shared__ uint32_t As[2][128 * ASTR];
    __shared__ uint32_t Bs[2][16 * BSTR];

    int z = blockIdx.z;
    A  += (long)z * sA;
    Bp += (long)z * sB;
    C  += (long)z * sC;

    int m0 = blockIdx.y * 128, n0 = blockIdx.x * 128;
    int tid = threadIdx.x;
    int warp = tid >> 5, lane = tid & 31;
    int wm = (warp >> 1) * 32;     // 0,32,64,96
    int wn = (warp & 1) * 64;      // 0,64
    int lr = lane >> 2, lc = lane & 3;

    float acc[2][8][4];
    #pragma unroll
    for (int i = 0; i < 2; i++)
        #pragma unroll
        for (int j = 0; j < 8; j++)
            #pragma unroll
            for (int q = 0; q < 4; q++) acc[i][j][q] = 0.f;

    uint4 ra[2], rb[2];

    // --- fetch tile at k0 into registers (tf32-converted, zero-filled OOB) ---
    auto fetch = [&](int k0) {
        #pragma unroll
        for (int j = 0; j < 2; j++) {
            int f = tid + j * 256;
            int row = f >> 2, c4 = (f & 3) * 4;
            int gm = m0 + row, gk = k0 + c4;
            uint4 v = make_uint4(0u, 0u, 0u, 0u);
            if (gm < M) {
                const float* p = A + (long)gm * lda + gk;
                if (gk + 3 < K && ((((uintptr_t)p) & 15) == 0)) {
                    float4 t = *(const float4*)p;
                    v.x = f2tf(t.x); v.y = f2tf(t.y); v.z = f2tf(t.z); v.w = f2tf(t.w);
                } else {
                    if (gk + 0 < K) v.x = f2tf(p[0]);
                    if (gk + 1 < K) v.y = f2tf(p[1]);
                    if (gk + 2 < K) v.z = f2tf(p[2]);
                    if (gk + 3 < K) v.w = f2tf(p[3]);
                }
            }
            ra[j] = v;
        }
        if (transB) {
            #pragma unroll
            for (int j = 0; j < 2; j++) {
                int f = tid + j * 256;
                int nn = f >> 2, k4 = (f & 3) * 4;
                int gn = n0 + nn, gk = k0 + k4;
                uint4 v = make_uint4(0u, 0u, 0u, 0u);
                if (gn < N) {
                    const float* p = Bp + (long)gn * ldb + gk;
                    if (gk + 3 < K && ((((uintptr_t)p) & 15) == 0)) {
                        float4 t = *(const float4*)p;
                        v.x = f2tf(t.x); v.y = f2tf(t.y); v.z = f2tf(t.z); v.w = f2tf(t.w);
                    } else {
                        if (gk + 0 < K) v.x = f2tf(p[0]);
                        if (gk + 1 < K) v.y = f2tf(p[1]);
                        if (gk + 2 < K) v.z = f2tf(p[2]);
                        if (gk + 3 < K) v.w = f2tf(p[3]);
                    }
                }
                rb[j] = v;
            }
        } else {
            #pragma unroll
            for (int j = 0; j < 2; j++) {
                int f = tid + j * 256;
                int kk = f >> 5, n4 = (f & 31) * 4;
                int gk = k0 + kk, gn = n0 + n4;
                uint4 v = make_uint4(0u, 0u, 0u, 0u);
                if (gk < K) {
                    const float* p = Bp + (long)gk * ldb + gn;
                    if (gn + 3 < N && ((((uintptr_t)p) & 15) == 0)) {
                        float4 t = *(const float4*)p;
                        v.x = f2tf(t.x); v.y = f2tf(t.y); v.z = f2tf(t.z); v.w = f2tf(t.w);
                    } else {
                        if (gn + 0 < N) v.x = f2tf(p[0]);
                        if (gn + 1 < N) v.y = f2tf(p[1]);
                        if (gn + 2 < N) v.z = f2tf(p[2]);
                        if (gn + 3 < N) v.w = f2tf(p[3]);
                    }
                }
                rb[j] = v;
            }
        }
    };

    auto stash = [&](int buf) {
        #pragma unroll
        for (int j = 0; j < 2; j++) {
            int f = tid + j * 256;
            int row = f >> 2, c4 = (f & 3) * 4;
            *(uint4*)&As[buf][row * ASTR + c4] = ra[j];
        }
        if (transB) {
            #pragma unroll
            for (int j = 0; j < 2; j++) {
                int f = tid + j * 256;
                int nn = f >> 2, k4 = (f & 3) * 4;
                Bs[buf][(k4 + 0) * BSTR + nn] = rb[j].x;
                Bs[buf][(k4 + 1) * BSTR + nn] = rb[j].y;
                Bs[buf][(k4 + 2) * BSTR + nn] = rb[j].z;
                Bs[buf][(k4 + 3) * BSTR + nn] = rb[j].w;
            }
        } else {
            #pragma unroll
            for (int j = 0; j < 2; j++) {
                int f = tid + j * 256;
                int kk = f >> 5, n4 = (f & 31) * 4;
                *(uint4*)&Bs[buf][kk * BSTR + n4] = rb[j];
            }
        }
    };

    fetch(0);
    stash(0);
    __syncthreads();

    int buf = 0;
    for (int k0 = 0; k0 < K; k0 += 16) {
        int knext = k0 + 16;
        if (knext < K) fetch(knext);

        #pragma unroll
        for (int kk = 0; kk < 2; kk++) {
            int kb = kk * 8;
            uint32_t af[2][4];
            uint32_t bfr[8][2];
            #pragma unroll
            for (int im = 0; im < 2; im++) {
                int r = wm + im * 16 + lr;
                af[im][0] = As[buf][r * ASTR + kb + lc];
                af[im][1] = As[buf][(r + 8) * ASTR + kb + lc];
                af[im][2] = As[buf][r * ASTR + kb + lc + 4];
                af[im][3] = As[buf][(r + 8) * ASTR + kb + lc + 4];
            }
            #pragma unroll
            for (int in_ = 0; in_ < 8; in_++) {
                int nn = wn + in_ * 8 + lr;
                bfr[in_][0] = Bs[buf][(kb + lc) * BSTR + nn];
                bfr[in_][1] = Bs[buf][(kb + lc + 4) * BSTR + nn];
            }
            #pragma unroll
            for (int im = 0; im < 2; im++)
                #pragma unroll
                for (int in_ = 0; in_ < 8; in_++)
                    mma_tf32(acc[im][in_], af[im], bfr[in_]);
        }

        if (knext < K) stash(buf ^ 1);
        __syncthreads();
        buf ^= 1;
    }

    // ---- epilogue ----
    if (resid) resid += (long)z * sR;
    #pragma unroll
    for (int im = 0; im < 2; im++) {
        #pragma unroll
        for (int rr = 0; rr < 2; rr++) {
            int gm = m0 + wm + im * 16 + lr + rr * 8;
            if (gm >= M) continue;
            float bm = biasM ? biasM[gm] : 0.f;
            #pragma unroll
            for (int in_ = 0; in_ < 8; in_++) {
                int gn = n0 + wn + in_ * 8 + 2 * lc;
                float v0 = acc[im][in_][rr * 2 + 0] + bm;
                float v1 = acc[im][in_][rr * 2 + 1] + bm;
                if (biasN) {
                    if (gn + 0 < N) v0 += biasN[gn + 0];
                    if (gn + 1 < N) v1 += biasN[gn + 1];
                }
                if (resid) {
                    if (gn + 0 < N) v0 += resid[(long)gm * ldc + gn + 0];
                    if (gn + 1 < N) v1 += resid[(long)gm * ldc + gn + 1];
                }
                if (act == 2) {
                    v0 = (v0 > 20.f) ? v0 : log1pf(__expf(v0));
                    v1 = (v1 > 20.f) ? v1 : log1pf(__expf(v1));
                }
                float* cp = &C[(long)gm * ldc + gn];
                if (gn + 1 < N && ((((uintptr_t)cp) & 7) == 0)) {
                    *(float2*)cp = make_float2(v0, v1);
                } else {
                    if (gn + 0 < N) cp[0] = v0;
                    if (gn + 1 < N) cp[1] = v1;
                }
            }
        }
    }
}

// ---------------- host side --------------------------------------------------
static void launch_gemm(const float* A, const float* B, float* C,
                        int M, int N, int K, int lda, int ldb, int ldc,
                        long sA, long sB, long sC, int batch, int transB,
                        const float* biasM, const float* biasN,
                        const float* resid, long sR, int act) {
    dim3 grid((N + 127) / 128, (M + 127) / 128, batch);
    gemm_tf32_kernel<<<grid, 256>>>(A, B, C, M, N, K, lda, ldb, ldc,
                                    sA, sB, sC, transB, biasM, biasN, resid, sR, act);
}

extern "C" void kernel_launch(void* const* d_in, const int* in_sizes, int n_in,
                              void* d_out, int out_size) {
    const float* x       = (const float*)d_in[0];
    const float* bn1_g   = (const float*)d_in[1];
    const float* bn1_b   = (const float*)d_in[2];
    const float* conv1_w = (const float*)d_in[3];
    const float* conv1_b = (const float*)d_in[4];
    const float* ln_w    = (const float*)d_in[5];
    const float* ln_b    = (const float*)d_in[6];
    const float* W_in    = (const float*)d_in[7];
    const float* convm_w = (const float*)d_in[8];
    const float* convm_b = (const float*)d_in[9];
    const float* W_x     = (const float*)d_in[10];
    const float* W_dt    = (const float*)d_in[11];
    const float* b_dt    = (const float*)d_in[12];
    const float* A_log   = (const float*)d_in[13];
    const float* D_p     = (const float*)d_in[14];
    const float* W_out   = (const float*)d_in[15];
    const float* bn3_g   = (const float*)d_in[16];
    const float* bn3_b   = (const float*)d_in[17];
    const float* conv3_w = (const float*)d_in[18];
    const float* conv3_b = (const float*)d_in[19];
    float* out = (float*)d_out;

    float *pm1, *pr1, *pcm1, *pcr1, *pmL, *prL, *pm3, *pr3, *pcm3, *pcr3;
    float *ph, *ph1, *poutn, *pxz, *pxc, *pxdbl, *pdt, *py, *pres;
    cudaGetSymbolAddress((void**)&pm1,  g_m1);
    cudaGetSymbolAddress((void**)&pr1,  g_r1);
    cudaGetSymbolAddress((void**)&pcm1, g_cm1);
    cudaGetSymbolAddress((void**)&pcr1, g_cr1);
    cudaGetSymbolAddress((void**)&pmL,  g_mL);
    cudaGetSymbolAddress((void**)&prL,  g_rL);
    cudaGetSymbolAddress((void**)&pm3,  g_m3);
    cudaGetSymbolAddress((void**)&pr3,  g_r3);
    cudaGetSymbolAddress((void**)&pcm3, g_cm3);
    cudaGetSymbolAddress((void**)&pcr3, g_cr3);
    cudaGetSymbolAddress((void**)&ph,    g_h);
    cudaGetSymbolAddress((void**)&ph1,   g_h1);
    cudaGetSymbolAddress((void**)&poutn, g_outn);
    cudaGetSymbolAddress((void**)&pxz,   g_xz);
    cudaGetSymbolAddress((void**)&pxc,   g_xc);
    cudaGetSymbolAddress((void**)&pxdbl, g_xdbl);
    cudaGetSymbolAddress((void**)&pdt,   g_dt);
    cudaGetSymbolAddress((void**)&py,    g_y);
    cudaGetSymbolAddress((void**)&pres,  g_res);

    const int EW_BLK = 256;
    const size_t nBCN = (size_t)ROWS * NDIM;
    const size_t nBLD = (size_t)ROWS * DIX;
    int gBCN = (int)((nBCN + EW_BLK - 1) / EW_BLK);
    int gBLD = (int)((nBLD + EW_BLK - 1) / EW_BLK);

    // ---- Block 1: inorm -> bnorm -> relu -> 1x1 conv ----
    rowstat_kernel<<<ROWS, 256>>>(x, pm1, pr1, NDIM, 1e-3f);
    chanstat_kernel<<<CCH, 256>>>(x, pm1, pr1, pcm1, pcr1, 1e-5f);
    normrelu_kernel<<<gBCN, EW_BLK>>>(x, pm1, pr1, pcm1, pcr1, bn1_g, bn1_b, ph);
    launch_gemm(conv1_w, ph, ph1, CCH, NDIM, CCH, CCH, NDIM, NDIM,
                0, (long)CCH * NDIM, (long)CCH * NDIM, BATCH, 0,
                conv1_b, nullptr, nullptr, 0, 0);

    // ---- LayerNorm over N ----
    rowstat_kernel<<<ROWS, 256>>>(ph1, pmL, prL, NDIM, 1e-5f);
    lnapply_kernel<<<gBCN, EW_BLK>>>(ph1, pmL, prL, ln_w, ln_b, poutn);

    // ---- Mamba ----
    launch_gemm(poutn, W_in, pxz, ROWS, DIN2, NDIM, NDIM, NDIM, DIN2,
                0, 0, 0, 1, 1, nullptr, nullptr, nullptr, 0, 0);
    convm_silu_kernel<<<gBLD, EW_BLK>>>(pxz, convm_w, convm_b, pxc);
    launch_gemm(pxc, W_x, pxdbl, ROWS, XCOLS, DIX, DIX, DIX, XCOLS,
                0, 0, 0, 1, 1, nullptr, nullptr, nullptr, 0, 0);
    launch_gemm(pxdbl, W_dt, pdt, ROWS, DIX, DTR, XCOLS, DTR, DIX,
                0, 0, 0, 1, 1, nullptr, b_dt, nullptr, 0, 2);
    scan_kernel<<<(BATCH * DIX + 255) / 256, 256>>>(pdt, pxc, pxdbl, pxz,
                                                    A_log, D_p, py);
    launch_gemm(py, W_out, pres, ROWS, NDIM, DIX, DIX, DIX, NDIM,
                0, 0, 0, 1, 1, nullptr, nullptr, ph1, 0, 0);

    // ---- Block 3 ----
    rowstat_kernel<<<ROWS, 256>>>(pres, pm3, pr3, NDIM, 1e-3f);
    chanstat_kernel<<<CCH, 256>>>(pres, pm3, pr3, pcm3, pcr3, 1e-5f);
    normrelu_kernel<<<gBCN, EW_BLK>>>(pres, pm3, pr3, pcm3, pcr3, bn3_g, bn3_b, ph);
    launch_gemm(conv3_w, ph, out, CCH, NDIM, CCH, CCH, NDIM, NDIM,
                0, (long)CCH * NDIM, (long)CCH * NDIM, BATCH, 0,
                conv3_b, nullptr, x, (long)CCH * NDIM, 0);
}

// round 8
// speedup vs baseline: 2.1283x; 1.1846x over previous
#include <cuda_runtime.h>
#include <math.h>
#include <stdint.h>

#define BATCH 16
#define CCH   128
#define NDIM  2000
#define SST   8
#define DCONVK 4
#define DIX   4000
#define DTR   125
#define XCOLS 141     // DTR + 2*SST
#define LSEQ  128     // sequence length for mamba = CCH
#define ROWS  2048    // BATCH*CCH = BATCH*LSEQ
#define DIN2  8000    // 2*DIX

// ---------------- scratch (static device memory; no allocations) -------------
__device__ float g_m1[ROWS], g_r1[ROWS];
__device__ float g_cm1[CCH], g_cr1[CCH];
__device__ float g_mL[ROWS], g_rL[ROWS];
__device__ float g_m3[ROWS], g_r3[ROWS];
__device__ float g_cm3[CCH], g_cr3[CCH];
__device__ float g_h   [(size_t)ROWS*NDIM];
__device__ float g_h1  [(size_t)ROWS*NDIM];
__device__ float g_outn[(size_t)ROWS*NDIM];
__device__ float g_xz  [(size_t)ROWS*DIN2];
__device__ float g_xc  [(size_t)ROWS*DIX];
__device__ float g_xdbl[(size_t)ROWS*XCOLS];
__device__ float g_dt  [(size_t)ROWS*DIX];
__device__ float g_y   [(size_t)ROWS*DIX];
__device__ float g_res [(size_t)ROWS*NDIM];

// ---------------- reductions -------------------------------------------------
__device__ __forceinline__ void block_reduce2(float& s, float& s2) {
    __shared__ float sh[16];
    #pragma unroll
    for (int o = 16; o; o >>= 1) {
        s  += __shfl_down_sync(0xffffffffu, s,  o);
        s2 += __shfl_down_sync(0xffffffffu, s2, o);
    }
    int w = threadIdx.x >> 5, lane = threadIdx.x & 31;
    if (lane == 0) { sh[w] = s; sh[8 + w] = s2; }
    __syncthreads();
    if (threadIdx.x == 0) {
        float S = 0.f, S2 = 0.f;
        int nw = blockDim.x >> 5;
        for (int i = 0; i < nw; i++) { S += sh[i]; S2 += sh[8 + i]; }
        sh[0] = S; sh[8] = S2;
    }
    __syncthreads();
    s = sh[0]; s2 = sh[8];
}

__global__ void rowstat_kernel(const float* __restrict__ x, float* __restrict__ mean,
                               float* __restrict__ rstd, int L, float eps) {
    int row = blockIdx.x;
    const float* p = x + (size_t)row * L;
    float s = 0.f, s2 = 0.f;
    for (int i = threadIdx.x; i < L; i += blockDim.x) {
        float v = p[i]; s += v; s2 += v * v;
    }
    block_reduce2(s, s2);
    if (threadIdx.x == 0) {
        float m = s / L;
        float var = s2 / L - m * m;
        mean[row] = m;
        rstd[row] = rsqrtf(var + eps);
    }
}

__global__ void chanstat_kernel(const float* __restrict__ x, const float* __restrict__ m,
                                const float* __restrict__ r, float* __restrict__ cmean,
                                float* __restrict__ crstd, float eps) {
    int c = blockIdx.x;
    float s = 0.f, s2 = 0.f;
    for (int idx = threadIdx.x; idx < BATCH * NDIM; idx += blockDim.x) {
        int b = idx / NDIM, n = idx - b * NDIM;
        int row = b * CCH + c;
        float v = (x[(size_t)row * NDIM + n] - m[row]) * r[row];
        s += v; s2 += v * v;
    }
    block_reduce2(s, s2);
    if (threadIdx.x == 0) {
        float mm = s / (BATCH * NDIM);
        float var = s2 / (BATCH * NDIM) - mm * mm;
        cmean[c] = mm;
        crstd[c] = rsqrtf(var + eps);
    }
}

__global__ void normrelu_kernel(const float* __restrict__ x, const float* __restrict__ m,
                                const float* __restrict__ r, const float* __restrict__ cm,
                                const float* __restrict__ cr, const float* __restrict__ g,
                                const float* __restrict__ bb, float* __restrict__ out) {
    size_t i = (size_t)blockIdx.x * blockDim.x + threadIdx.x;
    if (i >= (size_t)ROWS * NDIM) return;
    int row = (int)(i / NDIM);
    int c = row & (CCH - 1);
    float v = (x[i] - m[row]) * r[row];
    v = (v - cm[c]) * cr[c] * g[c] + bb[c];
    out[i] = fmaxf(v, 0.f);
}

__global__ void lnapply_kernel(const float* __restrict__ x, const float* __restrict__ m,
                               const float* __restrict__ r, const float* __restrict__ w,
                               const float* __restrict__ bb, float* __restrict__ out) {
    size_t i = (size_t)blockIdx.x * blockDim.x + threadIdx.x;
    if (i >= (size_t)ROWS * NDIM) return;
    int row = (int)(i / NDIM);
    int n = (int)(i - (size_t)row * NDIM);
    out[i] = (x[i] - m[row]) * r[row] * w[n] + bb[n];
}

__global__ void convm_silu_kernel(const float* __restrict__ xz, const float* __restrict__ cw,
                                  const float* __restrict__ cb, float* __restrict__ xc) {
    size_t i = (size_t)blockIdx.x * blockDim.x + threadIdx.x;
    if (i >= (size_t)ROWS * DIX) return;
    int d = (int)(i % DIX);
    size_t mrow = i / DIX;
    int l = (int)(mrow & (LSEQ - 1));
    size_t b = mrow >> 7;
    float acc = cb[d];
    #pragma unroll
    for (int k = 0; k < DCONVK; k++) {
        int ls = l + k - (DCONVK - 1);
        if (ls >= 0)
            acc += xz[(b * LSEQ + ls) * (size_t)DIN2 + d] * cw[d * DCONVK + k];
    }
    xc[i] = acc * (1.f / (1.f + __expf(-acc)));
}

__global__ void scan_kernel(const float* __restrict__ dt, const float* __restrict__ xc,
                            const float* __restrict__ xdbl, const float* __restrict__ xz,
                            const float* __restrict__ A_log, const float* __restrict__ D_p,
                            float* __restrict__ y) {
    int gidx = blockIdx.x * blockDim.x + threadIdx.x;
    if (gidx >= BATCH * DIX) return;
    int b = gidx / DIX, d = gidx - b * DIX;
    float A[SST], h[SST];
    #pragma unroll
    for (int s = 0; s < SST; s++) {
        A[s] = -expf(A_log[d * SST + s]);
        h[s] = 0.f;
    }
    float Dp = D_p[d];
    for (int l = 0; l < LSEQ; l++) {
        size_t m = (size_t)b * LSEQ + l;
        float dtv = dt[m * DIX + d];
        float u = xc[m * DIX + d];
        float du = dtv * u;
        const float* xr = xdbl + m * XCOLS;
        float yv = 0.f;
        #pragma unroll
        for (int s = 0; s < SST; s++) {
            h[s] = __expf(dtv * A[s]) * h[s] + du * xr[DTR + s];
            yv += h[s] * xr[DTR + SST + s];
        }
        float zv = xz[m * DIN2 + DIX + d];
        y[m * DIX + d] = (yv + u * Dp) * (zv / (1.f + __expf(-zv)));
    }
}

// ---------------- shared GEMM helpers ----------------------------------------
#define ASTR 20    // A-tile (and trans-B-tile) row stride in floats
#define BSTR 136   // notrans B-tile row stride in floats

__device__ __forceinline__ uint32_t f2tf(float x) {
    uint32_t r;
    asm("cvt.rna.tf32.f32 %0, %1;" : "=r"(r) : "f"(x));
    return r;
}

__device__ __forceinline__ void mma_tf32(float* c, const uint32_t* a, const uint32_t* b) {
    asm volatile(
        "mma.sync.aligned.m16n8k8.row.col.f32.tf32.tf32.f32 "
        "{%0,%1,%2,%3}, {%4,%5,%6,%7}, {%8,%9}, {%0,%1,%2,%3};\n"
        : "+f"(c[0]), "+f"(c[1]), "+f"(c[2]), "+f"(c[3])
        : "r"(a[0]), "r"(a[1]), "r"(a[2]), "r"(a[3]), "r"(b[0]), "r"(b[1]));
}

__device__ __forceinline__ void cpa16(uint32_t dst, const void* src, bool pred) {
    int sz = pred ? 16 : 0;
    asm volatile("cp.async.cg.shared.global [%0], [%1], 16, %2;\n"
                 :: "r"(dst), "l"(src), "r"(sz));
}
__device__ __forceinline__ void cp_commit() {
    asm volatile("cp.async.commit_group;\n");
}
template <int n>
__device__ __forceinline__ void cp_wait() {
    asm volatile("cp.async.wait_group %0;\n" :: "n"(n));
}

// shared epilogue
__device__ __forceinline__ void gemm_epilogue(
    float acc[2][8][4], float* C, int M, int N, int ldc,
    int m0, int n0, int wm, int wn, int lr, int lc,
    const float* biasM, const float* biasN, const float* resid, int act) {
    #pragma unroll
    for (int im = 0; im < 2; im++) {
        #pragma unroll
        for (int rr = 0; rr < 2; rr++) {
            int gm = m0 + wm + im * 16 + lr + rr * 8;
            if (gm >= M) continue;
            float bm = biasM ? biasM[gm] : 0.f;
            #pragma unroll
            for (int in_ = 0; in_ < 8; in_++) {
                int gn = n0 + wn + in_ * 8 + 2 * lc;
                float v0 = acc[im][in_][rr * 2 + 0] + bm;
                float v1 = acc[im][in_][rr * 2 + 1] + bm;
                if (biasN) {
                    if (gn + 0 < N) v0 += biasN[gn + 0];
                    if (gn + 1 < N) v1 += biasN[gn + 1];
                }
                if (resid) {
                    if (gn + 0 < N) v0 += resid[(long)gm * ldc + gn + 0];
                    if (gn + 1 < N) v1 += resid[(long)gm * ldc + gn + 1];
                }
                if (act == 2) {
                    // stable softplus: max(v,0) + log(1+exp(-|v|))
                    v0 = fmaxf(v0, 0.f) + __logf(1.f + __expf(-fabsf(v0)));
                    v1 = fmaxf(v1, 0.f) + __logf(1.f + __expf(-fabsf(v1)));
                }
                float* cp = &C[(long)gm * ldc + gn];
                if (gn + 1 < N && ((((uintptr_t)cp) & 7) == 0)) {
                    *(float2*)cp = make_float2(v0, v1);
                } else {
                    if (gn + 0 < N) cp[0] = v0;
                    if (gn + 1 < N) cp[1] = v1;
                }
            }
        }
    }
}

// ---------------- pipelined TF32 GEMM (aligned path, K%16==0) -----------------
// 3-stage cp.async pipeline, 128x128 tile, BK=16, 8 warps (4m x 2n).
#define STAGES 3
#define ASIZE  (128 * ASTR)   // 2560 floats
#define BSIZE  2560           // max(16*BSTR=2176, 128*ASTR=2560)
#define STG_W  (ASIZE + BSIZE)
#define PIPE_SMEM (STAGES * STG_W * 4)

__global__ void __launch_bounds__(256, 2) gemm_tf32_pipe(
    const float* __restrict__ A, const float* __restrict__ Bp, float* __restrict__ C,
    int M, int N, int K, int lda, int ldb, int ldc,
    long sA, long sB, long sC, int transB,
    const float* __restrict__ biasM, const float* __restrict__ biasN,
    const float* __restrict__ resid, long sR, int act) {
    extern __shared__ float sm[];
    uint32_t smbase = (uint32_t)__cvta_generic_to_shared(sm);

    int z = blockIdx.z;
    A  += (long)z * sA;
    Bp += (long)z * sB;
    C  += (long)z * sC;

    int m0 = blockIdx.y * 128, n0 = blockIdx.x * 128;
    int tid = threadIdx.x;
    int warp = tid >> 5, lane = tid & 31;
    int wm = (warp >> 1) * 32;
    int wn = (warp & 1) * 64;
    int lr = lane >> 2, lc = lane & 3;

    float acc[2][8][4];
    #pragma unroll
    for (int i = 0; i < 2; i++)
        #pragma unroll
        for (int j = 0; j < 8; j++)
            #pragma unroll
            for (int q = 0; q < 4; q++) acc[i][j][q] = 0.f;

    // precomputed per-thread load coordinates
    int a_row[2], a_c4[2];
    #pragma unroll
    for (int j = 0; j < 2; j++) {
        int f = tid + j * 256;
        a_row[j] = f >> 2;
        a_c4[j]  = (f & 3) * 4;
    }

    auto load_stage = [&](int k0, int st) {
        uint32_t abase = smbase + (uint32_t)(st * STG_W * 4);
        uint32_t bbase = abase + (uint32_t)(ASIZE * 4);
        #pragma unroll
        for (int j = 0; j < 2; j++) {
            int row = a_row[j], c4 = a_c4[j];
            int gm = m0 + row;
            cpa16(abase + (uint32_t)((row * ASTR + c4) * 4),
                  A + (long)gm * lda + k0 + c4, gm < M);
        }
        if (transB) {
            #pragma unroll
            for (int j = 0; j < 2; j++) {
                int nn = a_row[j], k4 = a_c4[j];
                int gn = n0 + nn;
                cpa16(bbase + (uint32_t)((nn * ASTR + k4) * 4),
                      Bp + (long)gn * ldb + k0 + k4, gn < N);
            }
        } else {
            #pragma unroll
            for (int j = 0; j < 2; j++) {
                int f = tid + j * 256;
                int kk = f >> 5, n4 = (f & 31) * 4;
                int gn = n0 + n4;
                cpa16(bbase + (uint32_t)((kk * BSTR + n4) * 4),
                      Bp + (long)(k0 + kk) * ldb + gn, gn < N);
            }
        }
    };

    int niter = K >> 4;   // K % 16 == 0 guaranteed by host

    #pragma unroll
    for (int s = 0; s < STAGES - 1; s++) {
        load_stage(s * 16, s);
        cp_commit();
    }

    for (int it = 0; it < niter; it++) {
        int kp = it + STAGES - 1;
        if (kp < niter) load_stage(kp * 16, kp % STAGES);
        cp_commit();
        cp_wait<STAGES - 1>();
        __syncthreads();

        int st = it % STAGES;
        const float* Asm = sm + st * STG_W;
        const float* Bsm = Asm + ASIZE;

        #pragma unroll
        for (int kk = 0; kk < 2; kk++) {
            int kb = kk * 8;
            uint32_t af[2][4];
            uint32_t bfr[8][2];
            #pragma unroll
            for (int im = 0; im < 2; im++) {
                int r = wm + im * 16 + lr;
                af[im][0] = f2tf(Asm[r * ASTR + kb + lc]);
                af[im][1] = f2tf(Asm[(r + 8) * ASTR + kb + lc]);
                af[im][2] = f2tf(Asm[r * ASTR + kb + lc + 4]);
                af[im][3] = f2tf(Asm[(r + 8) * ASTR + kb + lc + 4]);
            }
            if (transB) {
                #pragma unroll
                for (int in_ = 0; in_ < 8; in_++) {
                    int nn = wn + in_ * 8 + lr;
                    bfr[in_][0] = f2tf(Bsm[nn * ASTR + kb + lc]);
                    bfr[in_][1] = f2tf(Bsm[nn * ASTR + kb + lc + 4]);
                }
            } else {
                #pragma unroll
                for (int in_ = 0; in_ < 8; in_++) {
                    int nn = wn + in_ * 8 + lr;
                    bfr[in_][0] = f2tf(Bsm[(kb + lc) * BSTR + nn]);
                    bfr[in_][1] = f2tf(Bsm[(kb + lc + 4) * BSTR + nn]);
                }
            }
            #pragma unroll
            for (int im = 0; im < 2; im++)
                #pragma unroll
                for (int in_ = 0; in_ < 8; in_++)
                    mma_tf32(acc[im][in_], af[im], bfr[in_]);
        }
        __syncthreads();
    }

    if (resid) resid += (long)z * sR;
    gemm_epilogue(acc, C, M, N, ldc, m0, n0, wm, wn, lr, lc, biasM, biasN, resid, act);
}

// ---------------- fallback TF32 GEMM (unaligned / K%16!=0) --------------------
__global__ void __launch_bounds__(256, 2) gemm_tf32_kernel(
    const float* __restrict__ A, const float* __restrict__ Bp, float* __restrict__ C,
    int M, int N, int K, int lda, int ldb, int ldc,
    long sA, long sB, long sC, int transB,
    const float* __restrict__ biasM, const float* __restrict__ biasN,
    const float* __restrict__ resid, long sR, int act) {
    __shared__ uint32_t As[2][128 * ASTR];
    __shared__ uint32_t Bs[2][16 * BSTR];

    int z = blockIdx.z;
    A  += (long)z * sA;
    Bp += (long)z * sB;
    C  += (long)z * sC;

    int m0 = blockIdx.y * 128, n0 = blockIdx.x * 128;
    int tid = threadIdx.x;
    int warp = tid >> 5, lane = tid & 31;
    int wm = (warp >> 1) * 32;
    int wn = (warp & 1) * 64;
    int lr = lane >> 2, lc = lane & 3;

    float acc[2][8][4];
    #pragma unroll
    for (int i = 0; i < 2; i++)
        #pragma unroll
        for (int j = 0; j < 8; j++)
            #pragma unroll
            for (int q = 0; q < 4; q++) acc[i][j][q] = 0.f;

    uint4 ra[2], rb[2];

    auto fetch = [&](int k0) {
        #pragma unroll
        for (int j = 0; j < 2; j++) {
            int f = tid + j * 256;
            int row = f >> 2, c4 = (f & 3) * 4;
            int gm = m0 + row, gk = k0 + c4;
            uint4 v = make_uint4(0u, 0u, 0u, 0u);
            if (gm < M) {
                const float* p = A + (long)gm * lda + gk;
                if (gk + 0 < K) v.x = f2tf(p[0]);
                if (gk + 1 < K) v.y = f2tf(p[1]);
                if (gk + 2 < K) v.z = f2tf(p[2]);
                if (gk + 3 < K) v.w = f2tf(p[3]);
            }
            ra[j] = v;
        }
        if (transB) {
            #pragma unroll
            for (int j = 0; j < 2; j++) {
                int f = tid + j * 256;
                int nn = f >> 2, k4 = (f & 3) * 4;
                int gn = n0 + nn, gk = k0 + k4;
                uint4 v = make_uint4(0u, 0u, 0u, 0u);
                if (gn < N) {
                    const float* p = Bp + (long)gn * ldb + gk;
                    if (gk + 0 < K) v.x = f2tf(p[0]);
                    if (gk + 1 < K) v.y = f2tf(p[1]);
                    if (gk + 2 < K) v.z = f2tf(p[2]);
                    if (gk + 3 < K) v.w = f2tf(p[3]);
                }
                rb[j] = v;
            }
        } else {
            #pragma unroll
            for (int j = 0; j < 2; j++) {
                int f = tid + j * 256;
                int kk = f >> 5, n4 = (f & 31) * 4;
                int gk = k0 + kk, gn = n0 + n4;
                uint4 v = make_uint4(0u, 0u, 0u, 0u);
                if (gk < K) {
                    const float* p = Bp + (long)gk * ldb + gn;
                    if (gn + 0 < N) v.x = f2tf(p[0]);
                    if (gn + 1 < N) v.y = f2tf(p[1]);
                    if (gn + 2 < N) v.z = f2tf(p[2]);
                    if (gn + 3 < N) v.w = f2tf(p[3]);
                }
                rb[j] = v;
            }
        }
    };

    auto stash = [&](int buf) {
        #pragma unroll
        for (int j = 0; j < 2; j++) {
            int f = tid + j * 256;
            int row = f >> 2, c4 = (f & 3) * 4;
            *(uint4*)&As[buf][row * ASTR + c4] = ra[j];
        }
        if (transB) {
            #pragma unroll
            for (int j = 0; j < 2; j++) {
                int f = tid + j * 256;
                int nn = f >> 2, k4 = (f & 3) * 4;
                Bs[buf][(k4 + 0) * BSTR + nn] = rb[j].x;
                Bs[buf][(k4 + 1) * BSTR + nn] = rb[j].y;
                Bs[buf][(k4 + 2) * BSTR + nn] = rb[j].z;
                Bs[buf][(k4 + 3) * BSTR + nn] = rb[j].w;
            }
        } else {
            #pragma unroll
            for (int j = 0; j < 2; j++) {
                int f = tid + j * 256;
                int kk = f >> 5, n4 = (f & 31) * 4;
                *(uint4*)&Bs[buf][kk * BSTR + n4] = rb[j];
            }
        }
    };

    fetch(0);
    stash(0);
    __syncthreads();

    int buf = 0;
    for (int k0 = 0; k0 < K; k0 += 16) {
        int knext = k0 + 16;
        if (knext < K) fetch(knext);

        #pragma unroll
        for (int kk = 0; kk < 2; kk++) {
            int kb = kk * 8;
            uint32_t af[2][4];
            uint32_t bfr[8][2];
            #pragma unroll
            for (int im = 0; im < 2; im++) {
                int r = wm + im * 16 + lr;
                af[im][0] = As[buf][r * ASTR + kb + lc];
                af[im][1] = As[buf][(r + 8) * ASTR + kb + lc];
                af[im][2] = As[buf][r * ASTR + kb + lc + 4];
                af[im][3] = As[buf][(r + 8) * ASTR + kb + lc + 4];
            }
            #pragma unroll
            for (int in_ = 0; in_ < 8; in_++) {
                int nn = wn + in_ * 8 + lr;
                bfr[in_][0] = Bs[buf][(kb + lc) * BSTR + nn];
                bfr[in_][1] = Bs[buf][(kb + lc + 4) * BSTR + nn];
            }
            #pragma unroll
            for (int im = 0; im < 2; im++)
                #pragma unroll
                for (int in_ = 0; in_ < 8; in_++)
                    mma_tf32(acc[im][in_], af[im], bfr[in_]);
        }

        if (knext < K) stash(buf ^ 1);
        __syncthreads();
        buf ^= 1;
    }

    if (resid) resid += (long)z * sR;
    gemm_epilogue(acc, C, M, N, ldc, m0, n0, wm, wn, lr, lc, biasM, biasN, resid, act);
}

// ---------------- host side --------------------------------------------------
static void launch_gemm(const float* A, const float* B, float* C,
                        int M, int N, int K, int lda, int ldb, int ldc,
                        long sA, long sB, long sC, int batch, int transB,
                        const float* biasM, const float* biasN,
                        const float* resid, long sR, int act) {
    dim3 grid((N + 127) / 128, (M + 127) / 128, batch);
    bool aligned = (K % 16 == 0) && (lda % 4 == 0) && (ldb % 4 == 0) &&
                   (N % 4 == 0 || transB);
    if (aligned) {
        cudaFuncSetAttribute(gemm_tf32_pipe,
                             cudaFuncAttributeMaxDynamicSharedMemorySize, PIPE_SMEM);
        gemm_tf32_pipe<<<grid, 256, PIPE_SMEM>>>(A, B, C, M, N, K, lda, ldb, ldc,
                                                 sA, sB, sC, transB, biasM, biasN,
                                                 resid, sR, act);
    } else {
        gemm_tf32_kernel<<<grid, 256>>>(A, B, C, M, N, K, lda, ldb, ldc,
                                        sA, sB, sC, transB, biasM, biasN,
                                        resid, sR, act);
    }
}

extern "C" void kernel_launch(void* const* d_in, const int* in_sizes, int n_in,
                              void* d_out, int out_size) {
    const float* x       = (const float*)d_in[0];
    const float* bn1_g   = (const float*)d_in[1];
    const float* bn1_b   = (const float*)d_in[2];
    const float* conv1_w = (const float*)d_in[3];
    const float* conv1_b = (const float*)d_in[4];
    const float* ln_w    = (const float*)d_in[5];
    const float* ln_b    = (const float*)d_in[6];
    const float* W_in    = (const float*)d_in[7];
    const float* convm_w = (const float*)d_in[8];
    const float* convm_b = (const float*)d_in[9];
    const float* W_x     = (const float*)d_in[10];
    const float* W_dt    = (const float*)d_in[11];
    const float* b_dt    = (const float*)d_in[12];
    const float* A_log   = (const float*)d_in[13];
    const float* D_p     = (const float*)d_in[14];
    const float* W_out   = (const float*)d_in[15];
    const float* bn3_g   = (const float*)d_in[16];
    const float* bn3_b   = (const float*)d_in[17];
    const float* conv3_w = (const float*)d_in[18];
    const float* conv3_b = (const float*)d_in[19];
    float* out = (float*)d_out;

    float *pm1, *pr1, *pcm1, *pcr1, *pmL, *prL, *pm3, *pr3, *pcm3, *pcr3;
    float *ph, *ph1, *poutn, *pxz, *pxc, *pxdbl, *pdt, *py, *pres;
    cudaGetSymbolAddress((void**)&pm1,  g_m1);
    cudaGetSymbolAddress((void**)&pr1,  g_r1);
    cudaGetSymbolAddress((void**)&pcm1, g_cm1);
    cudaGetSymbolAddress((void**)&pcr1, g_cr1);
    cudaGetSymbolAddress((void**)&pmL,  g_mL);
    cudaGetSymbolAddress((void**)&prL,  g_rL);
    cudaGetSymbolAddress((void**)&pm3,  g_m3);
    cudaGetSymbolAddress((void**)&pr3,  g_r3);
    cudaGetSymbolAddress((void**)&pcm3, g_cm3);
    cudaGetSymbolAddress((void**)&pcr3, g_cr3);
    cudaGetSymbolAddress((void**)&ph,    g_h);
    cudaGetSymbolAddress((void**)&ph1,   g_h1);
    cudaGetSymbolAddress((void**)&poutn, g_outn);
    cudaGetSymbolAddress((void**)&pxz,   g_xz);
    cudaGetSymbolAddress((void**)&pxc,   g_xc);
    cudaGetSymbolAddress((void**)&pxdbl, g_xdbl);
    cudaGetSymbolAddress((void**)&pdt,   g_dt);
    cudaGetSymbolAddress((void**)&py,    g_y);
    cudaGetSymbolAddress((void**)&pres,  g_res);

    const int EW_BLK = 256;
    const size_t nBCN = (size_t)ROWS * NDIM;
    const size_t nBLD = (size_t)ROWS * DIX;
    int gBCN = (int)((nBCN + EW_BLK - 1) / EW_BLK);
    int gBLD = (int)((nBLD + EW_BLK - 1) / EW_BLK);

    // ---- Block 1: inorm -> bnorm -> relu -> 1x1 conv ----
    rowstat_kernel<<<ROWS, 256>>>(x, pm1, pr1, NDIM, 1e-3f);
    chanstat_kernel<<<CCH, 256>>>(x, pm1, pr1, pcm1, pcr1, 1e-5f);
    normrelu_kernel<<<gBCN, EW_BLK>>>(x, pm1, pr1, pcm1, pcr1, bn1_g, bn1_b, ph);
    launch_gemm(conv1_w, ph, ph1, CCH, NDIM, CCH, CCH, NDIM, NDIM,
                0, (long)CCH * NDIM, (long)CCH * NDIM, BATCH, 0,
                conv1_b, nullptr, nullptr, 0, 0);

    // ---- LayerNorm over N ----
    rowstat_kernel<<<ROWS, 256>>>(ph1, pmL, prL, NDIM, 1e-5f);
    lnapply_kernel<<<gBCN, EW_BLK>>>(ph1, pmL, prL, ln_w, ln_b, poutn);

    // ---- Mamba ----
    launch_gemm(poutn, W_in, pxz, ROWS, DIN2, NDIM, NDIM, NDIM, DIN2,
                0, 0, 0, 1, 1, nullptr, nullptr, nullptr, 0, 0);
    convm_silu_kernel<<<gBLD, EW_BLK>>>(pxz, convm_w, convm_b, pxc);
    launch_gemm(pxc, W_x, pxdbl, ROWS, XCOLS, DIX, DIX, DIX, XCOLS,
                0, 0, 0, 1, 1, nullptr, nullptr, nullptr, 0, 0);
    launch_gemm(pxdbl, W_dt, pdt, ROWS, DIX, DTR, XCOLS, DTR, DIX,
                0, 0, 0, 1, 1, nullptr, b_dt, nullptr, 0, 2);
    scan_kernel<<<(BATCH * DIX + 255) / 256, 256>>>(pdt, pxc, pxdbl, pxz,
                                                    A_log, D_p, py);
    launch_gemm(py, W_out, pres, ROWS, NDIM, DIX, DIX, DIX, NDIM,
                0, 0, 0, 1, 1, nullptr, nullptr, ph1, 0, 0);

    // ---- Block 3 ----
    rowstat_kernel<<<ROWS, 256>>>(pres, pm3, pr3, NDIM, 1e-3f);
    chanstat_kernel<<<CCH, 256>>>(pres, pm3, pr3, pcm3, pcr3, 1e-5f);
    normrelu_kernel<<<gBCN, EW_BLK>>>(pres, pm3, pr3, pcm3, pcr3, bn3_g, bn3_b, ph);
    launch_gemm(conv3_w, ph, out, CCH, NDIM, CCH, CCH, NDIM, NDIM,
                0, (long)CCH * NDIM, (long)CCH * NDIM, BATCH, 0,
                conv3_b, nullptr, x, (long)CCH * NDIM, 0);
}

// round 9
// speedup vs baseline: 3.5217x; 1.6547x over previous
#include <cuda_runtime.h>
#include <math.h>
#include <stdint.h>

#define BATCH 16
#define CCH   128
#define NDIM  2000
#define SST   8
#define DCONVK 4
#define DIX   4000
#define DTR   125
#define XCOLS 141     // DTR + 2*SST
#define LSEQ  128     // sequence length for mamba = CCH
#define ROWS  2048    // BATCH*CCH = BATCH*LSEQ
#define DIN2  8000    // 2*DIX

// ---------------- scratch (static device memory; no allocations) -------------
__device__ float g_m1[ROWS], g_r1[ROWS];
__device__ float g_cm1[CCH], g_cr1[CCH];
__device__ float g_mL[ROWS], g_rL[ROWS];
__device__ float g_m3[ROWS], g_r3[ROWS];
__device__ float g_cm3[CCH], g_cr3[CCH];
__device__ float g_h   [(size_t)ROWS*NDIM];
__device__ float g_h1  [(size_t)ROWS*NDIM];
__device__ float g_outn[(size_t)ROWS*NDIM];
__device__ float g_xz  [(size_t)ROWS*DIN2];
__device__ float g_xc  [(size_t)ROWS*DIX];
__device__ float g_xdbl[(size_t)ROWS*XCOLS];
__device__ float g_dt  [(size_t)ROWS*DIX];
__device__ float g_y   [(size_t)ROWS*DIX];
__device__ float g_res [(size_t)ROWS*NDIM];
// pre-rounded (tf32) weight copies
__device__ float g_win [(size_t)DIN2*NDIM];
__device__ float g_wout[(size_t)NDIM*DIX];
__device__ float g_wx  [(size_t)XCOLS*DIX];
__device__ float g_c1w [CCH*CCH];
__device__ float g_c3w [CCH*CCH];

__device__ __forceinline__ uint32_t f2tf(float x) {
    uint32_t r;
    asm("cvt.rna.tf32.f32 %0, %1;" : "=r"(r) : "f"(x));
    return r;
}
__device__ __forceinline__ float rtf(float x) { return __uint_as_float(f2tf(x)); }

// ---------------- reductions -------------------------------------------------
__device__ __forceinline__ void block_reduce2(float& s, float& s2) {
    __shared__ float sh[16];
    #pragma unroll
    for (int o = 16; o; o >>= 1) {
        s  += __shfl_down_sync(0xffffffffu, s,  o);
        s2 += __shfl_down_sync(0xffffffffu, s2, o);
    }
    int w = threadIdx.x >> 5, lane = threadIdx.x & 31;
    if (lane == 0) { sh[w] = s; sh[8 + w] = s2; }
    __syncthreads();
    if (threadIdx.x == 0) {
        float S = 0.f, S2 = 0.f;
        int nw = blockDim.x >> 5;
        for (int i = 0; i < nw; i++) { S += sh[i]; S2 += sh[8 + i]; }
        sh[0] = S; sh[8] = S2;
    }
    __syncthreads();
    s = sh[0]; s2 = sh[8];
}

__global__ void rowstat_kernel(const float* __restrict__ x, float* __restrict__ mean,
                               float* __restrict__ rstd, int L, float eps) {
    int row = blockIdx.x;
    const float* p = x + (size_t)row * L;
    float s = 0.f, s2 = 0.f;
    for (int i = threadIdx.x; i < L; i += blockDim.x) {
        float v = p[i]; s += v; s2 += v * v;
    }
    block_reduce2(s, s2);
    if (threadIdx.x == 0) {
        float m = s / L;
        float var = s2 / L - m * m;
        mean[row] = m;
        rstd[row] = rsqrtf(var + eps);
    }
}

__global__ void chanstat_kernel(const float* __restrict__ x, const float* __restrict__ m,
                                const float* __restrict__ r, float* __restrict__ cmean,
                                float* __restrict__ crstd, float eps) {
    int c = blockIdx.x;
    float s = 0.f, s2 = 0.f;
    for (int idx = threadIdx.x; idx < BATCH * NDIM; idx += blockDim.x) {
        int b = idx / NDIM, n = idx - b * NDIM;
        int row = b * CCH + c;
        float v = (x[(size_t)row * NDIM + n] - m[row]) * r[row];
        s += v; s2 += v * v;
    }
    block_reduce2(s, s2);
    if (threadIdx.x == 0) {
        float mm = s / (BATCH * NDIM);
        float var = s2 / (BATCH * NDIM) - mm * mm;
        cmean[c] = mm;
        crstd[c] = rsqrtf(var + eps);
    }
}

// stores tf32-rounded output (GEMM operand)
__global__ void normrelu_kernel(const float* __restrict__ x, const float* __restrict__ m,
                                const float* __restrict__ r, const float* __restrict__ cm,
                                const float* __restrict__ cr, const float* __restrict__ g,
                                const float* __restrict__ bb, float* __restrict__ out) {
    size_t i = (size_t)blockIdx.x * blockDim.x + threadIdx.x;
    if (i >= (size_t)ROWS * NDIM) return;
    int row = (int)(i / NDIM);
    int c = row & (CCH - 1);
    float v = (x[i] - m[row]) * r[row];
    v = (v - cm[c]) * cr[c] * g[c] + bb[c];
    out[i] = rtf(fmaxf(v, 0.f));
}

// stores tf32-rounded output (GEMM operand)
__global__ void lnapply_kernel(const float* __restrict__ x, const float* __restrict__ m,
                               const float* __restrict__ r, const float* __restrict__ w,
                               const float* __restrict__ bb, float* __restrict__ out) {
    size_t i = (size_t)blockIdx.x * blockDim.x + threadIdx.x;
    if (i >= (size_t)ROWS * NDIM) return;
    int row = (int)(i / NDIM);
    int n = (int)(i - (size_t)row * NDIM);
    out[i] = rtf((x[i] - m[row]) * r[row] * w[n] + bb[n]);
}

// stores tf32-rounded xc (GEMM operand; also scan input)
__global__ void convm_silu_kernel(const float* __restrict__ xz, const float* __restrict__ cw,
                                  const float* __restrict__ cb, float* __restrict__ xc) {
    size_t i = (size_t)blockIdx.x * blockDim.x + threadIdx.x;
    if (i >= (size_t)ROWS * DIX) return;
    int d = (int)(i % DIX);
    size_t mrow = i / DIX;
    int l = (int)(mrow & (LSEQ - 1));
    size_t b = mrow >> 7;
    float acc = cb[d];
    #pragma unroll
    for (int k = 0; k < DCONVK; k++) {
        int ls = l + k - (DCONVK - 1);
        if (ls >= 0)
            acc += xz[(b * LSEQ + ls) * (size_t)DIN2 + d] * cw[d * DCONVK + k];
    }
    xc[i] = rtf(acc * (1.f / (1.f + __expf(-acc))));
}

// stores tf32-rounded y (GEMM operand)
__global__ void scan_kernel(const float* __restrict__ dt, const float* __restrict__ xc,
                            const float* __restrict__ xdbl, const float* __restrict__ xz,
                            const float* __restrict__ A_log, const float* __restrict__ D_p,
                            float* __restrict__ y) {
    int gidx = blockIdx.x * blockDim.x + threadIdx.x;
    if (gidx >= BATCH * DIX) return;
    int b = gidx / DIX, d = gidx - b * DIX;
    float A[SST], h[SST];
    #pragma unroll
    for (int s = 0; s < SST; s++) {
        A[s] = -expf(A_log[d * SST + s]);
        h[s] = 0.f;
    }
    float Dp = D_p[d];
    for (int l = 0; l < LSEQ; l++) {
        size_t m = (size_t)b * LSEQ + l;
        float dtv = dt[m * DIX + d];
        float u = xc[m * DIX + d];
        float du = dtv * u;
        const float* xr = xdbl + m * XCOLS;
        float yv = 0.f;
        #pragma unroll
        for (int s = 0; s < SST; s++) {
            h[s] = __expf(dtv * A[s]) * h[s] + du * xr[DTR + s];
            yv += h[s] * xr[DTR + SST + s];
        }
        float zv = xz[m * DIN2 + DIX + d];
        y[m * DIX + d] = rtf((yv + u * Dp) * (zv / (1.f + __expf(-zv))));
    }
}

// pre-round a tensor to tf32 (RN)
__global__ void round_tf32_kernel(const float* __restrict__ src, float* __restrict__ dst,
                                  long n) {
    long i = (long)blockIdx.x * blockDim.x + threadIdx.x;
    long stride = (long)gridDim.x * blockDim.x;
    for (; i < n; i += stride) dst[i] = rtf(src[i]);
}

// ---------------- shared GEMM helpers ----------------------------------------
#define BSTRN 136   // notrans B-tile row stride in floats

__device__ __forceinline__ void mma_tf32(float* c, const uint32_t* a, const uint32_t* b) {
    asm volatile(
        "mma.sync.aligned.m16n8k8.row.col.f32.tf32.tf32.f32 "
        "{%0,%1,%2,%3}, {%4,%5,%6,%7}, {%8,%9}, {%0,%1,%2,%3};\n"
        : "+f"(c[0]), "+f"(c[1]), "+f"(c[2]), "+f"(c[3])
        : "r"(a[0]), "r"(a[1]), "r"(a[2]), "r"(a[3]), "r"(b[0]), "r"(b[1]));
}

__device__ __forceinline__ void cpa16(uint32_t dst, const void* src, bool pred) {
    int sz = pred ? 16 : 0;
    asm volatile("cp.async.cg.shared.global [%0], [%1], 16, %2;\n"
                 :: "r"(dst), "l"(src), "r"(sz));
}
__device__ __forceinline__ void cp_commit() {
    asm volatile("cp.async.commit_group;\n");
}
template <int n>
__device__ __forceinline__ void cp_wait() {
    asm volatile("cp.async.wait_group %0;\n" :: "n"(n));
}

__device__ __forceinline__ void gemm_epilogue(
    float acc[2][8][4], float* C, int M, int N, int ldc,
    int m0, int n0, int wm, int wn, int lr, int lc,
    const float* biasM, const float* biasN, const float* resid, int act) {
    #pragma unroll
    for (int im = 0; im < 2; im++) {
        #pragma unroll
        for (int rr = 0; rr < 2; rr++) {
            int gm = m0 + wm + im * 16 + lr + rr * 8;
            if (gm >= M) continue;
            float bm = biasM ? biasM[gm] : 0.f;
            #pragma unroll
            for (int in_ = 0; in_ < 8; in_++) {
                int gn = n0 + wn + in_ * 8 + 2 * lc;
                float v0 = acc[im][in_][rr * 2 + 0] + bm;
                float v1 = acc[im][in_][rr * 2 + 1] + bm;
                if (biasN) {
                    if (gn + 0 < N) v0 += biasN[gn + 0];
                    if (gn + 1 < N) v1 += biasN[gn + 1];
                }
                if (resid) {
                    if (gn + 0 < N) v0 += resid[(long)gm * ldc + gn + 0];
                    if (gn + 1 < N) v1 += resid[(long)gm * ldc + gn + 1];
                }
                if (act == 2) {
                    v0 = fmaxf(v0, 0.f) + __logf(1.f + __expf(-fabsf(v0)));
                    v1 = fmaxf(v1, 0.f) + __logf(1.f + __expf(-fabsf(v1)));
                }
                float* cp = &C[(long)gm * ldc + gn];
                if (gn + 1 < N && ((((uintptr_t)cp) & 7) == 0)) {
                    *(float2*)cp = make_float2(v0, v1);
                } else {
                    if (gn + 0 < N) cp[0] = v0;
                    if (gn + 1 < N) cp[1] = v1;
                }
            }
        }
    }
}

// ---------------- pipelined TF32 GEMM (aligned, K%16==0, pre-rounded data) ----
// 4-stage cp.async pipeline, 128x128 tile, BK=16, 8 warps (4m x 2n).
// TRANSB=1: B n-major in smem, k-slot remap (2lc,2lc+1) -> float2 fragment loads.
#define STAGES 4
#define ASZ    3072                 // A region floats (128*24 max)
#define BSZ    3072                 // B region floats (max of 128*24, 16*136)
#define STG_W  (ASZ + BSZ)
#define PIPE_SMEM (STAGES * STG_W * 4)

template <int TRANSB>
__global__ void __launch_bounds__(256, 2) gemm_tf32_pipe(
    const float* __restrict__ A, const float* __restrict__ Bp, float* __restrict__ C,
    int M, int N, int K, int lda, int ldb, int ldc,
    long sA, long sB, long sC,
    const float* __restrict__ biasM, const float* __restrict__ biasN,
    const float* __restrict__ resid, long sR, int act) {
    constexpr int ASTR = TRANSB ? 24 : 20;   // conflict-free for each read pattern
    extern __shared__ float sm[];
    uint32_t smbase = (uint32_t)__cvta_generic_to_shared(sm);

    int z = blockIdx.z;
    A  += (long)z * sA;
    Bp += (long)z * sB;
    C  += (long)z * sC;

    int m0 = blockIdx.y * 128, n0 = blockIdx.x * 128;
    int tid = threadIdx.x;
    int warp = tid >> 5, lane = tid & 31;
    int wm = (warp >> 1) * 32;
    int wn = (warp & 1) * 64;
    int lr = lane >> 2, lc = lane & 3;

    float acc[2][8][4];
    #pragma unroll
    for (int i = 0; i < 2; i++)
        #pragma unroll
        for (int j = 0; j < 8; j++)
            #pragma unroll
            for (int q = 0; q < 4; q++) acc[i][j][q] = 0.f;

    int a_row[2], a_c4[2];
    #pragma unroll
    for (int j = 0; j < 2; j++) {
        int f = tid + j * 256;
        a_row[j] = f >> 2;
        a_c4[j]  = (f & 3) * 4;
    }

    auto load_stage = [&](int k0, int st) {
        uint32_t abase = smbase + (uint32_t)(st * STG_W * 4);
        uint32_t bbase = abase + (uint32_t)(ASZ * 4);
        #pragma unroll
        for (int j = 0; j < 2; j++) {
            int row = a_row[j], c4 = a_c4[j];
            int gm = m0 + row;
            cpa16(abase + (uint32_t)((row * ASTR + c4) * 4),
                  A + (long)gm * lda + k0 + c4, gm < M);
        }
        if (TRANSB) {
            #pragma unroll
            for (int j = 0; j < 2; j++) {
                int nn = a_row[j], k4 = a_c4[j];
                int gn = n0 + nn;
                cpa16(bbase + (uint32_t)((nn * ASTR + k4) * 4),
                      Bp + (long)gn * ldb + k0 + k4, gn < N);
            }
        } else {
            #pragma unroll
            for (int j = 0; j < 2; j++) {
                int f = tid + j * 256;
                int kk = f >> 5, n4 = (f & 31) * 4;
                int gn = n0 + n4;
                cpa16(bbase + (uint32_t)((kk * BSTRN + n4) * 4),
                      Bp + (long)(k0 + kk) * ldb + gn, gn < N);
            }
        }
    };

    int niter = K >> 4;

    #pragma unroll
    for (int s = 0; s < STAGES - 1; s++) {
        load_stage(s * 16, s);
        cp_commit();
    }

    for (int it = 0; it < niter; it++) {
        int kp = it + STAGES - 1;
        if (kp < niter) load_stage(kp * 16, kp % STAGES);
        cp_commit();
        cp_wait<STAGES - 1>();
        __syncthreads();

        int st = it % STAGES;
        const float* Asm = sm + st * STG_W;
        const float* Bsm = Asm + ASZ;

        #pragma unroll
        for (int kk = 0; kk < 2; kk++) {
            int kb = kk * 8;
            uint32_t af[2][4];
            uint32_t bfr[8][2];
            if (TRANSB) {
                // k-slot remap: slot lc -> phys 2lc, slot lc+4 -> phys 2lc+1
                #pragma unroll
                for (int im = 0; im < 2; im++) {
                    int r = wm + im * 16 + lr;
                    uint2 v0 = *(const uint2*)&Asm[r * ASTR + kb + 2 * lc];
                    uint2 v1 = *(const uint2*)&Asm[(r + 8) * ASTR + kb + 2 * lc];
                    af[im][0] = v0.x; af[im][1] = v1.x;
                    af[im][2] = v0.y; af[im][3] = v1.y;
                }
                #pragma unroll
                for (int in_ = 0; in_ < 8; in_++) {
                    int nn = wn + in_ * 8 + lr;
                    uint2 w = *(const uint2*)&Bsm[nn * ASTR + kb + 2 * lc];
                    bfr[in_][0] = w.x; bfr[in_][1] = w.y;
                }
            } else {
                const uint32_t* Au = (const uint32_t*)Asm;
                const uint32_t* Bu = (const uint32_t*)Bsm;
                #pragma unroll
                for (int im = 0; im < 2; im++) {
                    int r = wm + im * 16 + lr;
                    af[im][0] = Au[r * ASTR + kb + lc];
                    af[im][1] = Au[(r + 8) * ASTR + kb + lc];
                    af[im][2] = Au[r * ASTR + kb + lc + 4];
                    af[im][3] = Au[(r + 8) * ASTR + kb + lc + 4];
                }
                #pragma unroll
                for (int in_ = 0; in_ < 8; in_++) {
                    int nn = wn + in_ * 8 + lr;
                    bfr[in_][0] = Bu[(kb + lc) * BSTRN + nn];
                    bfr[in_][1] = Bu[(kb + lc + 4) * BSTRN + nn];
                }
            }
            #pragma unroll
            for (int im = 0; im < 2; im++)
                #pragma unroll
                for (int in_ = 0; in_ < 8; in_++)
                    mma_tf32(acc[im][in_], af[im], bfr[in_]);
        }
        __syncthreads();
    }

    if (resid) resid += (long)z * sR;
    gemm_epilogue(acc, C, M, N, ldc, m0, n0, wm, wn, lr, lc, biasM, biasN, resid, act);
}

// ---------------- fallback TF32 GEMM (unaligned / K%16!=0) — W_dt only --------
#define ASTRF 20
__global__ void __launch_bounds__(256, 2) gemm_tf32_kernel(
    const float* __restrict__ A, const float* __restrict__ Bp, float* __restrict__ C,
    int M, int N, int K, int lda, int ldb, int ldc,
    long sA, long sB, long sC, int transB,
    const float* __restrict__ biasM, const float* __restrict__ biasN,
    const float* __restrict__ resid, long sR, int act) {
    __shared__ uint32_t As[2][128 * ASTRF];
    __shared__ uint32_t Bs[2][16 * BSTRN];

    int z = blockIdx.z;
    A  += (long)z * sA;
    Bp += (long)z * sB;
    C  += (long)z * sC;

    int m0 = blockIdx.y * 128, n0 = blockIdx.x * 128;
    int tid = threadIdx.x;
    int warp = tid >> 5, lane = tid & 31;
    int wm = (warp >> 1) * 32;
    int wn = (warp & 1) * 64;
    int lr = lane >> 2, lc = lane & 3;

    float acc[2][8][4];
    #pragma unroll
    for (int i = 0; i < 2; i++)
        #pragma unroll
        for (int j = 0; j < 8; j++)
            #pragma unroll
            for (int q = 0; q < 4; q++) acc[i][j][q] = 0.f;

    uint4 ra[2], rb[2];

    auto fetch = [&](int k0) {
        #pragma unroll
        for (int j = 0; j < 2; j++) {
            int f = tid + j * 256;
            int row = f >> 2, c4 = (f & 3) * 4;
            int gm = m0 + row, gk = k0 + c4;
            uint4 v = make_uint4(0u, 0u, 0u, 0u);
            if (gm < M) {
                const float* p = A + (long)gm * lda + gk;
                if (gk + 0 < K) v.x = f2tf(p[0]);
                if (gk + 1 < K) v.y = f2tf(p[1]);
                if (gk + 2 < K) v.z = f2tf(p[2]);
                if (gk + 3 < K) v.w = f2tf(p[3]);
            }
            ra[j] = v;
        }
        if (transB) {
            #pragma unroll
            for (int j = 0; j < 2; j++) {
                int f = tid + j * 256;
                int nn = f >> 2, k4 = (f & 3) * 4;
                int gn = n0 + nn, gk = k0 + k4;
                uint4 v = make_uint4(0u, 0u, 0u, 0u);
                if (gn < N) {
                    const float* p = Bp + (long)gn * ldb + gk;
                    if (gk + 0 < K) v.x = f2tf(p[0]);
                    if (gk + 1 < K) v.y = f2tf(p[1]);
                    if (gk + 2 < K) v.z = f2tf(p[2]);
                    if (gk + 3 < K) v.w = f2tf(p[3]);
                }
                rb[j] = v;
            }
        } else {
            #pragma unroll
            for (int j = 0; j < 2; j++) {
                int f = tid + j * 256;
                int kk = f >> 5, n4 = (f & 31) * 4;
                int gk = k0 + kk, gn = n0 + n4;
                uint4 v = make_uint4(0u, 0u, 0u, 0u);
                if (gk < K) {
                    const float* p = Bp + (long)gk * ldb + gn;
                    if (gn + 0 < N) v.x = f2tf(p[0]);
                    if (gn + 1 < N) v.y = f2tf(p[1]);
                    if (gn + 2 < N) v.z = f2tf(p[2]);
                    if (gn + 3 < N) v.w = f2tf(p[3]);
                }
                rb[j] = v;
            }
        }
    };

    auto stash = [&](int buf) {
        #pragma unroll
        for (int j = 0; j < 2; j++) {
            int f = tid + j * 256;
            int row = f >> 2, c4 = (f & 3) * 4;
            *(uint4*)&As[buf][row * ASTRF + c4] = ra[j];
        }
        if (transB) {
            #pragma unroll
            for (int j = 0; j < 2; j++) {
                int f = tid + j * 256;
                int nn = f >> 2, k4 = (f & 3) * 4;
                Bs[buf][(k4 + 0) * BSTRN + nn] = rb[j].x;
                Bs[buf][(k4 + 1) * BSTRN + nn] = rb[j].y;
                Bs[buf][(k4 + 2) * BSTRN + nn] = rb[j].z;
                Bs[buf][(k4 + 3) * BSTRN + nn] = rb[j].w;
            }
        } else {
            #pragma unroll
            for (int j = 0; j < 2; j++) {
                int f = tid + j * 256;
                int kk = f >> 5, n4 = (f & 31) * 4;
                *(uint4*)&Bs[buf][kk * BSTRN + n4] = rb[j];
            }
        }
    };

    fetch(0);
    stash(0);
    __syncthreads();

    int buf = 0;
    for (int k0 = 0; k0 < K; k0 += 16) {
        int knext = k0 + 16;
        if (knext < K) fetch(knext);

        #pragma unroll
        for (int kk = 0; kk < 2; kk++) {
            int kb = kk * 8;
            uint32_t af[2][4];
            uint32_t bfr[8][2];
            #pragma unroll
            for (int im = 0; im < 2; im++) {
                int r = wm + im * 16 + lr;
                af[im][0] = As[buf][r * ASTRF + kb + lc];
                af[im][1] = As[buf][(r + 8) * ASTRF + kb + lc];
                af[im][2] = As[buf][r * ASTRF + kb + lc + 4];
                af[im][3] = As[buf][(r + 8) * ASTRF + kb + lc + 4];
            }
            #pragma unroll
            for (int in_ = 0; in_ < 8; in_++) {
                int nn = wn + in_ * 8 + lr;
                bfr[in_][0] = Bs[buf][(kb + lc) * BSTRN + nn];
                bfr[in_][1] = Bs[buf][(kb + lc + 4) * BSTRN + nn];
            }
            #pragma unroll
            for (int im = 0; im < 2; im++)
                #pragma unroll
                for (int in_ = 0; in_ < 8; in_++)
                    mma_tf32(acc[im][in_], af[im], bfr[in_]);
        }

        if (knext < K) stash(buf ^ 1);
        __syncthreads();
        buf ^= 1;
    }

    if (resid) resid += (long)z * sR;
    gemm_epilogue(acc, C, M, N, ldc, m0, n0, wm, wn, lr, lc, biasM, biasN, resid, act);
}

// ---------------- host side --------------------------------------------------
static void launch_gemm(const float* A, const float* B, float* C,
                        int M, int N, int K, int lda, int ldb, int ldc,
                        long sA, long sB, long sC, int batch, int transB,
                        const float* biasM, const float* biasN,
                        const float* resid, long sR, int act) {
    dim3 grid((N + 127) / 128, (M + 127) / 128, batch);
    bool aligned = (K % 16 == 0) && (lda % 4 == 0) && (ldb % 4 == 0) &&
                   (N % 4 == 0 || transB);
    if (aligned) {
        if (transB) {
            cudaFuncSetAttribute(gemm_tf32_pipe<1>,
                                 cudaFuncAttributeMaxDynamicSharedMemorySize, PIPE_SMEM);
            gemm_tf32_pipe<1><<<grid, 256, PIPE_SMEM>>>(A, B, C, M, N, K, lda, ldb, ldc,
                                                        sA, sB, sC, biasM, biasN,
                                                        resid, sR, act);
        } else {
            cudaFuncSetAttribute(gemm_tf32_pipe<0>,
                                 cudaFuncAttributeMaxDynamicSharedMemorySize, PIPE_SMEM);
            gemm_tf32_pipe<0><<<grid, 256, PIPE_SMEM>>>(A, B, C, M, N, K, lda, ldb, ldc,
                                                        sA, sB, sC, biasM, biasN,
                                                        resid, sR, act);
        }
    } else {
        gemm_tf32_kernel<<<grid, 256>>>(A, B, C, M, N, K, lda, ldb, ldc,
                                        sA, sB, sC, transB, biasM, biasN,
                                        resid, sR, act);
    }
}

extern "C" void kernel_launch(void* const* d_in, const int* in_sizes, int n_in,
                              void* d_out, int out_size) {
    const float* x       = (const float*)d_in[0];
    const float* bn1_g   = (const float*)d_in[1];
    const float* bn1_b   = (const float*)d_in[2];
    const float* conv1_w = (const float*)d_in[3];
    const float* conv1_b = (const float*)d_in[4];
    const float* ln_w    = (const float*)d_in[5];
    const float* ln_b    = (const float*)d_in[6];
    const float* W_in    = (const float*)d_in[7];
    const float* convm_w = (const float*)d_in[8];
    const float* convm_b = (const float*)d_in[9];
    const float* W_x     = (const float*)d_in[10];
    const float* W_dt    = (const float*)d_in[11];
    const float* b_dt    = (const float*)d_in[12];
    const float* A_log   = (const float*)d_in[13];
    const float* D_p     = (const float*)d_in[14];
    const float* W_out   = (const float*)d_in[15];
    const float* bn3_g   = (const float*)d_in[16];
    const float* bn3_b   = (const float*)d_in[17];
    const float* conv3_w = (const float*)d_in[18];
    const float* conv3_b = (const float*)d_in[19];
    float* out = (float*)d_out;

    float *pm1, *pr1, *pcm1, *pcr1, *pmL, *prL, *pm3, *pr3, *pcm3, *pcr3;
    float *ph, *ph1, *poutn, *pxz, *pxc, *pxdbl, *pdt, *py, *pres;
    float *pwin, *pwout, *pwx, *pc1w, *pc3w;
    cudaGetSymbolAddress((void**)&pm1,  g_m1);
    cudaGetSymbolAddress((void**)&pr1,  g_r1);
    cudaGetSymbolAddress((void**)&pcm1, g_cm1);
    cudaGetSymbolAddress((void**)&pcr1, g_cr1);
    cudaGetSymbolAddress((void**)&pmL,  g_mL);
    cudaGetSymbolAddress((void**)&prL,  g_rL);
    cudaGetSymbolAddress((void**)&pm3,  g_m3);
    cudaGetSymbolAddress((void**)&pr3,  g_r3);
    cudaGetSymbolAddress((void**)&pcm3, g_cm3);
    cudaGetSymbolAddress((void**)&pcr3, g_cr3);
    cudaGetSymbolAddress((void**)&ph,    g_h);
    cudaGetSymbolAddress((void**)&ph1,   g_h1);
    cudaGetSymbolAddress((void**)&poutn, g_outn);
    cudaGetSymbolAddress((void**)&pxz,   g_xz);
    cudaGetSymbolAddress((void**)&pxc,   g_xc);
    cudaGetSymbolAddress((void**)&pxdbl, g_xdbl);
    cudaGetSymbolAddress((void**)&pdt,   g_dt);
    cudaGetSymbolAddress((void**)&py,    g_y);
    cudaGetSymbolAddress((void**)&pres,  g_res);
    cudaGetSymbolAddress((void**)&pwin,  g_win);
    cudaGetSymbolAddress((void**)&pwout, g_wout);
    cudaGetSymbolAddress((void**)&pwx,   g_wx);
    cudaGetSymbolAddress((void**)&pc1w,  g_c1w);
    cudaGetSymbolAddress((void**)&pc3w,  g_c3w);

    const int EW_BLK = 256;
    const size_t nBCN = (size_t)ROWS * NDIM;
    const size_t nBLD = (size_t)ROWS * DIX;
    int gBCN = (int)((nBCN + EW_BLK - 1) / EW_BLK);
    int gBLD = (int)((nBLD + EW_BLK - 1) / EW_BLK);

    // ---- pre-round weights to tf32 ----
    round_tf32_kernel<<<2048, 256>>>(W_in,  pwin,  (long)DIN2 * NDIM);
    round_tf32_kernel<<<2048, 256>>>(W_out, pwout, (long)NDIM * DIX);
    round_tf32_kernel<<<512,  256>>>(W_x,   pwx,   (long)XCOLS * DIX);
    round_tf32_kernel<<<64,   256>>>(conv1_w, pc1w, (long)CCH * CCH);
    round_tf32_kernel<<<64,   256>>>(conv3_w, pc3w, (long)CCH * CCH);

    // ---- Block 1: inorm -> bnorm -> relu -> 1x1 conv ----
    rowstat_kernel<<<ROWS, 256>>>(x, pm1, pr1, NDIM, 1e-3f);
    chanstat_kernel<<<CCH, 256>>>(x, pm1, pr1, pcm1, pcr1, 1e-5f);
    normrelu_kernel<<<gBCN, EW_BLK>>>(x, pm1, pr1, pcm1, pcr1, bn1_g, bn1_b, ph);
    launch_gemm(pc1w, ph, ph1, CCH, NDIM, CCH, CCH, NDIM, NDIM,
                0, (long)CCH * NDIM, (long)CCH * NDIM, BATCH, 0,
                conv1_b, nullptr, nullptr, 0, 0);

    // ---- LayerNorm over N ----
    rowstat_kernel<<<ROWS, 256>>>(ph1, pmL, prL, NDIM, 1e-5f);
    lnapply_kernel<<<gBCN, EW_BLK>>>(ph1, pmL, prL, ln_w, ln_b, poutn);

    // ---- Mamba ----
    launch_gemm(poutn, pwin, pxz, ROWS, DIN2, NDIM, NDIM, NDIM, DIN2,
                0, 0, 0, 1, 1, nullptr, nullptr, nullptr, 0, 0);
    convm_silu_kernel<<<gBLD, EW_BLK>>>(pxz, convm_w, convm_b, pxc);
    launch_gemm(pxc, pwx, pxdbl, ROWS, XCOLS, DIX, DIX, DIX, XCOLS,
                0, 0, 0, 1, 1, nullptr, nullptr, nullptr, 0, 0);
    launch_gemm(pxdbl, W_dt, pdt, ROWS, DIX, DTR, XCOLS, DTR, DIX,
                0, 0, 0, 1, 1, nullptr, b_dt, nullptr, 0, 2);
    scan_kernel<<<(BATCH * DIX + 255) / 256, 256>>>(pdt, pxc, pxdbl, pxz,
                                                    A_log, D_p, py);
    launch_gemm(py, pwout, pres, ROWS, NDIM, DIX, DIX, DIX, NDIM,
                0, 0, 0, 1, 1, nullptr, nullptr, ph1, 0, 0);

    // ---- Block 3 ----
    rowstat_kernel<<<ROWS, 256>>>(pres, pm3, pr3, NDIM, 1e-3f);
    chanstat_kernel<<<CCH, 256>>>(pres, pm3, pr3, pcm3, pcr3, 1e-5f);
    normrelu_kernel<<<gBCN, EW_BLK>>>(pres, pm3, pr3, pcm3, pcr3, bn3_g, bn3_b, ph);
    launch_gemm(pc3w, ph, out, CCH, NDIM, CCH, CCH, NDIM, NDIM,
                0, (long)CCH * NDIM, (long)CCH * NDIM, BATCH, 0,
                conv3_b, nullptr, x, (long)CCH * NDIM, 0);
}